// round 13
// baseline (speedup 1.0000x reference)
#include <cuda_runtime.h>
#include <cuda_bf16.h>
#include <cuda_fp16.h>

// ---------------------------------------------------------------------------
// BSAM self-attention via mma.sync (bf16 QK, fp16 PV), fp32 conv front.
//   Q = conv3x3(A1_B, w1*log2e, b1*log2e) -> g_Qs [b][p][hi32|lo32] bf16
//   K = conv3x3(A1_C, w2,b2)              -> g_Ks [b][p][hi32|lo32] bf16
//   V = conv3x3(A1_C, w3,b3)              -> g_V  [b][p][64] fp16
//   S = Q.K (3-way bf16 split); online per-row max softmax (base-2);
//   P fp16; O += P V. out = (O/l)^T + A1_C
// R12: software-pipelined chunk loop (softmax -> QK(kb+1) -> PV(kb)) with
//      triple-buffered K/V; pack merged into conv (2-kernel launch).
// ---------------------------------------------------------------------------

#define NB   4
#define NC   64
#define HW   64
#define NPIX 4096

typedef unsigned long long u64;
typedef unsigned u32;

__device__ __align__(16) __nv_bfloat16 g_Qs[NB * NPIX * 64];
__device__ __align__(16) __nv_bfloat16 g_Ks[NB * NPIX * 64];
__device__ __align__(16) __half        g_V [NB * NPIX * 64];
__device__ __align__(16) float g_wpack[64 * 9 * 128];
__device__ __align__(16) float g_bias[128];

// ---- packed f32x2 helpers (conv) -------------------------------------------
__device__ __forceinline__ u64 ffma2(u64 a, u64 b, u64 c) {
    u64 d; asm("fma.rn.f32x2 %0, %1, %2, %3;" : "=l"(d) : "l"(a), "l"(b), "l"(c));
    return d;
}
__device__ __forceinline__ u64 fpack2(float lo, float hi) {
    u64 d; asm("mov.b64 %0, {%1, %2};" : "=l"(d) : "f"(lo), "f"(hi));
    return d;
}
__device__ __forceinline__ float2 funpack2(u64 v) {
    float2 r; asm("mov.b64 {%0, %1}, %2;" : "=f"(r.x), "=f"(r.y) : "l"(v));
    return r;
}
__device__ __forceinline__ float ex2f(float x) {
    float y; asm("ex2.approx.f32 %0, %1;" : "=f"(y) : "f"(x));
    return y;
}

// ---- cp.async / mma / ldmatrix ----------------------------------------------
__device__ __forceinline__ void cp_async16(void* sdst, const void* gsrc) {
    u32 sa = (u32)__cvta_generic_to_shared(sdst);
    asm volatile("cp.async.cg.shared.global [%0], [%1], 16;" :: "r"(sa), "l"(gsrc));
}
#define CP_COMMIT() asm volatile("cp.async.commit_group;")
#define CP_WAIT0()  asm volatile("cp.async.wait_group 0;")
#define CP_WAIT1()  asm volatile("cp.async.wait_group 1;")

__device__ __forceinline__ void mma_bf16(float& c0, float& c1, float& c2, float& c3,
                                         u32 a0, u32 a1, u32 a2, u32 a3,
                                         u32 b0, u32 b1) {
    asm volatile(
        "mma.sync.aligned.m16n8k16.row.col.f32.bf16.bf16.f32 "
        "{%0,%1,%2,%3}, {%4,%5,%6,%7}, {%8,%9}, {%0,%1,%2,%3};"
        : "+f"(c0), "+f"(c1), "+f"(c2), "+f"(c3)
        : "r"(a0), "r"(a1), "r"(a2), "r"(a3), "r"(b0), "r"(b1));
}
__device__ __forceinline__ void mma_f16(float& c0, float& c1, float& c2, float& c3,
                                        u32 a0, u32 a1, u32 a2, u32 a3,
                                        u32 b0, u32 b1) {
    asm volatile(
        "mma.sync.aligned.m16n8k16.row.col.f32.f16.f16.f32 "
        "{%0,%1,%2,%3}, {%4,%5,%6,%7}, {%8,%9}, {%0,%1,%2,%3};"
        : "+f"(c0), "+f"(c1), "+f"(c2), "+f"(c3)
        : "r"(a0), "r"(a1), "r"(a2), "r"(a3), "r"(b0), "r"(b1));
}
__device__ __forceinline__ void ldsm4(u32* r, u32 saddr) {
    asm volatile("ldmatrix.sync.aligned.m8n8.x4.shared.b16 {%0,%1,%2,%3}, [%4];"
        : "=r"(r[0]), "=r"(r[1]), "=r"(r[2]), "=r"(r[3]) : "r"(saddr));
}
__device__ __forceinline__ void ldsm4t(u32* r, u32 saddr) {
    asm volatile("ldmatrix.sync.aligned.m8n8.x4.trans.shared.b16 {%0,%1,%2,%3}, [%4];"
        : "=r"(r[0]), "=r"(r[1]), "=r"(r[2]), "=r"(r[3]) : "r"(saddr));
}
__device__ __forceinline__ u32 h2u(__half2 h) {
    return *reinterpret_cast<u32*>(&h);
}

#define LOG2E 1.4426950408889634f

// ---------------------------------------------------------------------------
// Conv (+ fused weight pack). block=(row y, batch b), 128 thr, 2 pixels/thr.
// Every block redundantly packs g_wpack/g_bias (identical values -> benign);
// reads use plain loads (self-written global data).
// ---------------------------------------------------------------------------
#define CONV_SMEM (2 * 64 * 3 * 66 * 4)

__global__ __launch_bounds__(128)
void conv_kernel(const float* __restrict__ A1B, const float* __restrict__ A1C,
                 const float* __restrict__ w1, const float* __restrict__ b1,
                 const float* __restrict__ w2, const float* __restrict__ b2,
                 const float* __restrict__ w3, const float* __restrict__ b3) {
    extern __shared__ float smem[];
    float* sB = smem;
    float* sC = smem + 64 * 3 * 66;

    const int y   = blockIdx.x;
    const int b   = blockIdx.y;
    const int tid = threadIdx.x;

    // ---- fused pack: co 0..31 = w1*log2e, 32..63 = w2, 64..127 = w3 ---------
    if (tid < 128) {
        g_bias[tid] = (tid < 32) ? __ldg(b1 + tid) * LOG2E
                    : (tid < 64) ? __ldg(b2 + tid - 32) : __ldg(b3 + tid - 64);
    }
    for (int idx = tid; idx < 64 * 9 * 128; idx += 128) {
        int co = idx & 127;
        int t  = idx >> 7;
        int ci = t / 9;
        int k  = t % 9;
        float v;
        if (co < 32)       v = __ldg(w1 + (co * 64 + ci) * 9 + k) * LOG2E;
        else if (co < 64)  v = __ldg(w2 + ((co - 32) * 64 + ci) * 9 + k);
        else               v = __ldg(w3 + ((co - 64) * 64 + ci) * 9 + k);
        g_wpack[idx] = v;
    }

    // ---- stage input rows ----------------------------------------------------
    for (int idx = tid; idx < 64 * 3 * 66; idx += 128) {
        int ci  = idx / 198;
        int rem = idx % 198;
        int r   = rem / 66;
        int xx  = rem % 66;
        int yy  = y + r - 1;
        int x   = xx - 1;
        bool ok = (yy >= 0) && (yy < HW) && (x >= 0) && (x < HW);
        float vb = 0.f, vc = 0.f;
        if (ok) {
            int gi = ((b * 64 + ci) * HW + yy) * HW + x;
            vb = __ldg(A1B + gi);
            vc = __ldg(A1C + gi);
        }
        sB[idx] = vb;
        sC[idx] = vc;
    }
    __syncthreads();   // orders pack writes + smem staging for the whole block

    const int x0 = tid & 31;
    const int x1 = x0 + 32;
    const int g  = tid >> 5;
    const float* sIn = (g == 0) ? sB : sC;

    #pragma unroll
    for (int pass = 0; pass < 2; ++pass) {
        const int co0 = g * 32 + pass * 16;
        const u64* bp = reinterpret_cast<const u64*>(g_bias + co0);
        u64 acc0[8], acc1[8];
        #pragma unroll
        for (int u = 0; u < 8; ++u) { acc0[u] = bp[u]; acc1[u] = bp[u]; }

        for (int ci = 0; ci < 64; ++ci) {
            #pragma unroll
            for (int dy = 0; dy < 3; ++dy) {
                const float* row = sIn + (ci * 3 + dy) * 66;
                float a0 = row[x0], a1 = row[x0 + 1], a2 = row[x0 + 2];
                float c0 = row[x1], c1 = row[x1 + 1], c2 = row[x1 + 2];
                #pragma unroll
                for (int dx = 0; dx < 3; ++dx) {
                    float ivA = (dx == 0) ? a0 : (dx == 1) ? a1 : a2;
                    float ivB = (dx == 0) ? c0 : (dx == 1) ? c1 : c2;
                    u64 iA = fpack2(ivA, ivA);
                    u64 iB = fpack2(ivB, ivB);
                    const ulonglong2* wq = reinterpret_cast<const ulonglong2*>(
                        g_wpack + ((ci * 3 + dy) * 3 + dx) * 128 + co0);
                    ulonglong2 wA = wq[0];
                    ulonglong2 wB = wq[1];
                    ulonglong2 wC = wq[2];
                    ulonglong2 wD = wq[3];
                    acc0[0] = ffma2(iA, wA.x, acc0[0]); acc1[0] = ffma2(iB, wA.x, acc1[0]);
                    acc0[1] = ffma2(iA, wA.y, acc0[1]); acc1[1] = ffma2(iB, wA.y, acc1[1]);
                    acc0[2] = ffma2(iA, wB.x, acc0[2]); acc1[2] = ffma2(iB, wB.x, acc1[2]);
                    acc0[3] = ffma2(iA, wB.y, acc0[3]); acc1[3] = ffma2(iB, wB.y, acc1[3]);
                    acc0[4] = ffma2(iA, wC.x, acc0[4]); acc1[4] = ffma2(iB, wC.x, acc1[4]);
                    acc0[5] = ffma2(iA, wC.y, acc0[5]); acc1[5] = ffma2(iB, wC.y, acc1[5]);
                    acc0[6] = ffma2(iA, wD.x, acc0[6]); acc1[6] = ffma2(iB, wD.x, acc1[6]);
                    acc0[7] = ffma2(iA, wD.y, acc0[7]); acc1[7] = ffma2(iB, wD.y, acc1[7]);
                }
            }
        }

        #pragma unroll
        for (int pix = 0; pix < 2; ++pix) {
            const u64* acc = pix ? acc1 : acc0;
            const int p = y * HW + (pix ? x1 : x0);
            if (g <= 1) {
                __nv_bfloat16* dst = (g == 0 ? g_Qs : g_Ks)
                                   + (size_t)(b * NPIX + p) * 64 + (co0 & 31);
                #pragma unroll
                for (int u = 0; u < 8; ++u) {
                    float2 v = funpack2(acc[u]);
                    __nv_bfloat162 h = __floats2bfloat162_rn(v.x, v.y);
                    __nv_bfloat162 l = __floats2bfloat162_rn(
                        v.x - __bfloat162float(h.x), v.y - __bfloat162float(h.y));
                    *reinterpret_cast<__nv_bfloat162*>(dst + 2 * u)      = h;
                    *reinterpret_cast<__nv_bfloat162*>(dst + 32 + 2 * u) = l;
                }
            } else {
                __half* dst = g_V + (size_t)(b * NPIX + p) * 64 + (co0 - 64);
                #pragma unroll
                for (int u = 0; u < 8; ++u) {
                    float2 v = funpack2(acc[u]);
                    *reinterpret_cast<__half2*>(dst + 2 * u) =
                        __floats2half2_rn(v.x, v.y);
                }
            }
        }
    }
}

// ---------------------------------------------------------------------------
// Tensor-core flash attention, software-pipelined. 128 thr = 4 warps.
// Loop body: softmax(kb) -> [wait] -> QK(kb+1) -> PV(kb). Triple-buffered K/V
// (prefetch distance 2, wait_group 1) keeps cp.async latency covered.
// SMEM rows padded to 144B: Q@0 | K0/K1/K2 @9216.. | V0/V1/V2 @36864..
// Of[64][65]f32 overlays the K region for the epilogue.
// ---------------------------------------------------------------------------
#define SM_K(j) (9216 + (j) * 9216)
#define SM_V(j) (36864 + (j) * 9216)
#define ATTN_SMEM (7 * 9216)

__device__ __forceinline__ void attn_ldtile(char* dst, const char* src, int tid) {
    #pragma unroll
    for (int f = tid; f < 512; f += 128) {
        int r = f >> 3, s = (f & 7) * 16;
        cp_async16(dst + r * 144 + s, src + r * 128 + s);
    }
}

__global__ __launch_bounds__(128)
void attn_kernel(const float* __restrict__ A1C, float* __restrict__ out) {
    extern __shared__ __align__(16) char sm[];
    char* Qs  = sm;
    float* Of = reinterpret_cast<float*>(sm + 9216);

    const int rb   = blockIdx.x;
    const int b    = blockIdx.y;
    const int tid  = threadIdx.x;
    const int lane = tid & 31;
    const int w    = tid >> 5;
    const int q0   = rb * 64;
    const char* gQ = (const char*)(g_Qs + (size_t)(b * NPIX + q0) * 64);
    const char* gK = (const char*)(g_Ks + (size_t)b * NPIX * 64);
    const char* gV = (const char*)(g_V  + (size_t)b * NPIX * 64);

    // ---- prologue: group A {Q,K0,V0}, group B {K1,V1} -------------------------
    attn_ldtile(Qs, gQ, tid);
    attn_ldtile(sm + SM_K(0), gK, tid);
    attn_ldtile(sm + SM_V(0), gV, tid);
    CP_COMMIT();
    attn_ldtile(sm + SM_K(1), gK + 64 * 128, tid);
    attn_ldtile(sm + SM_V(1), gV + 64 * 128, tid);
    CP_COMMIT();
    CP_WAIT1();            // group A complete
    __syncthreads();

    // ---- Q fragments (resident for the whole kernel) --------------------------
    const u32 qrow  = w * 16 + ((lane >> 3) & 1) * 8 + (lane & 7);
    const u32 qcol8 = (lane >> 4) * 8;
    const u32 qbase = (u32)__cvta_generic_to_shared(Qs) + qrow * 144;
    u32 Ah[2][4], Al[2][4];
    ldsm4(Ah[0], qbase + (0  + qcol8) * 2);
    ldsm4(Ah[1], qbase + (16 + qcol8) * 2);
    ldsm4(Al[0], qbase + (32 + qcol8) * 2);
    ldsm4(Al[1], qbase + (48 + qcol8) * 2);

    const u32 koff = (lane & 7) * 144 + (((lane >> 3) & 1) * 8 + (lane >> 4) * 16) * 2;
    const u32 voff = (((lane >> 3) & 1) * 8 + (lane & 7)) * 144 + (lane >> 4) * 16;
    const u32 smb  = (u32)__cvta_generic_to_shared(sm);

    float o[8][4] = {};
    float lsum0 = 0.f, lsum1 = 0.f;
    float m0 = -1e30f, m1 = -1e30f;
    float c[8][4] = {};

    // ---- QK(0) -----------------------------------------------------------------
    {
        const u32 kbase = smb + SM_K(0) + koff;
        #pragma unroll
        for (int nt = 0; nt < 8; ++nt) {
            u32 bh[4], bl[4];
            u32 ra = kbase + nt * 8 * 144;
            ldsm4(bh, ra);
            ldsm4(bl, ra + 64);
            mma_bf16(c[nt][0], c[nt][1], c[nt][2], c[nt][3],
                     Ah[0][0], Ah[0][1], Ah[0][2], Ah[0][3], bh[0], bh[1]);
            mma_bf16(c[nt][0], c[nt][1], c[nt][2], c[nt][3],
                     Ah[1][0], Ah[1][1], Ah[1][2], Ah[1][3], bh[2], bh[3]);
            mma_bf16(c[nt][0], c[nt][1], c[nt][2], c[nt][3],
                     Ah[0][0], Ah[0][1], Ah[0][2], Ah[0][3], bl[0], bl[1]);
            mma_bf16(c[nt][0], c[nt][1], c[nt][2], c[nt][3],
                     Ah[1][0], Ah[1][1], Ah[1][2], Ah[1][3], bl[2], bl[3]);
            mma_bf16(c[nt][0], c[nt][1], c[nt][2], c[nt][3],
                     Al[0][0], Al[0][1], Al[0][2], Al[0][3], bh[0], bh[1]);
            mma_bf16(c[nt][0], c[nt][1], c[nt][2], c[nt][3],
                     Al[1][0], Al[1][1], Al[1][2], Al[1][3], bh[2], bh[3]);
        }
    }

    for (int kb = 0; kb < 64; ++kb) {
        const int bcur = kb % 3;
        const int bnxt = (kb + 1) % 3;
        const int bld  = (kb + 2) % 3;

        __syncthreads();   // all PV(kb-1) reads of V[bld] done before overwrite

        if (kb < 62) {
            const char* gKn = gK + (size_t)(kb + 2) * 64 * 128;
            const char* gVn = gV + (size_t)(kb + 2) * 64 * 128;
            attn_ldtile(sm + SM_K(bld), gKn, tid);
            attn_ldtile(sm + SM_V(bld), gVn, tid);
            CP_COMMIT();
        }

        // ---- online per-row max + softmax + P fp16 -----------------------------
        float mx0 = -1e30f, mx1 = -1e30f;
        #pragma unroll
        for (int nt = 0; nt < 8; ++nt) {
            mx0 = fmaxf(mx0, fmaxf(c[nt][0], c[nt][1]));
            mx1 = fmaxf(mx1, fmaxf(c[nt][2], c[nt][3]));
        }
        mx0 = fmaxf(mx0, __shfl_xor_sync(0xffffffffu, mx0, 1));
        mx0 = fmaxf(mx0, __shfl_xor_sync(0xffffffffu, mx0, 2));
        mx1 = fmaxf(mx1, __shfl_xor_sync(0xffffffffu, mx1, 1));
        mx1 = fmaxf(mx1, __shfl_xor_sync(0xffffffffu, mx1, 2));
        float mn0 = fmaxf(m0, mx0), mn1 = fmaxf(m1, mx1);
        if (mn0 > m0 || mn1 > m1) {
            float a0 = ex2f(m0 - mn0), a1 = ex2f(m1 - mn1);
            lsum0 *= a0; lsum1 *= a1;
            #pragma unroll
            for (int ct = 0; ct < 8; ++ct) {
                o[ct][0] *= a0; o[ct][1] *= a0;
                o[ct][2] *= a1; o[ct][3] *= a1;
            }
            m0 = mn0; m1 = mn1;
        }
        u32 Ph[4][4];
        #pragma unroll
        for (int nt = 0; nt < 8; ++nt) {
            float e0 = ex2f(c[nt][0] - m0);
            float e1 = ex2f(c[nt][1] - m0);
            float e2 = ex2f(c[nt][2] - m1);
            float e3 = ex2f(c[nt][3] - m1);
            lsum0 += e0 + e1;
            lsum1 += e2 + e3;
            int kt = nt >> 1, q = (nt & 1) * 2;
            Ph[kt][q]     = h2u(__floats2half2_rn(e0, e1));
            Ph[kt][q + 1] = h2u(__floats2half2_rn(e2, e3));
        }

        // ---- QK(kb+1): refill c while Ph feeds PV -------------------------------
        if (kb < 63) {
            if (kb < 62) CP_WAIT1();   // K(kb+1)'s group complete (kb+2 in flight)
            else         CP_WAIT0();   // last group drained
            __syncthreads();
            const u32 kbase = smb + SM_K(bnxt) + koff;
            #pragma unroll
            for (int nt = 0; nt < 8; ++nt) {
                u32 bh[4], bl[4];
                u32 ra = kbase + nt * 8 * 144;
                ldsm4(bh, ra);
                ldsm4(bl, ra + 64);
                float s0 = 0.f, s1 = 0.f, s2 = 0.f, s3 = 0.f;
                mma_bf16(s0, s1, s2, s3,
                         Ah[0][0], Ah[0][1], Ah[0][2], Ah[0][3], bh[0], bh[1]);
                mma_bf16(s0, s1, s2, s3,
                         Ah[1][0], Ah[1][1], Ah[1][2], Ah[1][3], bh[2], bh[3]);
                mma_bf16(s0, s1, s2, s3,
                         Ah[0][0], Ah[0][1], Ah[0][2], Ah[0][3], bl[0], bl[1]);
                mma_bf16(s0, s1, s2, s3,
                         Ah[1][0], Ah[1][1], Ah[1][2], Ah[1][3], bl[2], bl[3]);
                mma_bf16(s0, s1, s2, s3,
                         Al[0][0], Al[0][1], Al[0][2], Al[0][3], bh[0], bh[1]);
                mma_bf16(s0, s1, s2, s3,
                         Al[1][0], Al[1][1], Al[1][2], Al[1][3], bh[2], bh[3]);
                c[nt][0] = s0; c[nt][1] = s1; c[nt][2] = s2; c[nt][3] = s3;
            }
        }

        // ---- PV(kb) --------------------------------------------------------------
        const u32 vbase = smb + SM_V(bcur) + voff;
        #pragma unroll
        for (int kt = 0; kt < 4; ++kt) {
            #pragma unroll
            for (int cb = 0; cb < 4; ++cb) {
                u32 vr[4];
                ldsm4t(vr, vbase + kt * 16 * 144 + cb * 32);
                float* oa = o[2 * cb];
                float* ob = o[2 * cb + 1];
                mma_f16(oa[0], oa[1], oa[2], oa[3],
                        Ph[kt][0], Ph[kt][1], Ph[kt][2], Ph[kt][3], vr[0], vr[1]);
                mma_f16(ob[0], ob[1], ob[2], ob[3],
                        Ph[kt][0], Ph[kt][1], Ph[kt][2], Ph[kt][3], vr[2], vr[3]);
            }
        }
    }

    // ---- l reduction across the quad ------------------------------------------
    lsum0 += __shfl_xor_sync(0xffffffffu, lsum0, 1);
    lsum0 += __shfl_xor_sync(0xffffffffu, lsum0, 2);
    lsum1 += __shfl_xor_sync(0xffffffffu, lsum1, 1);
    lsum1 += __shfl_xor_sync(0xffffffffu, lsum1, 2);

    __syncthreads();   // all PV reads done before Of overlays the K region

    // ---- stage O/l into SMEM [row][ch] (stride 65) -------------------------------
    {
        float inv0 = 1.f / lsum0, inv1 = 1.f / lsum1;
        int r0 = w * 16 + (lane >> 2);
        int cc = (lane & 3) * 2;
        #pragma unroll
        for (int ct = 0; ct < 8; ++ct) {
            Of[r0 * 65 + ct * 8 + cc]           = o[ct][0] * inv0;
            Of[r0 * 65 + ct * 8 + cc + 1]       = o[ct][1] * inv0;
            Of[(r0 + 8) * 65 + ct * 8 + cc]     = o[ct][2] * inv1;
            Of[(r0 + 8) * 65 + ct * 8 + cc + 1] = o[ct][3] * inv1;
        }
    }
    __syncthreads();

    // ---- coalesced transpose-out + residual ---------------------------------------
    {
        int ch = tid >> 1, seg = (tid & 1) * 32;
        int gbase = (b * 64 + ch) * NPIX + q0 + seg;
        #pragma unroll
        for (int ww = 0; ww < 32; ww += 4) {
            float4 r = *reinterpret_cast<const float4*>(A1C + gbase + ww);
            float4 oo;
            oo.x = Of[(seg + ww + 0) * 65 + ch] + r.x;
            oo.y = Of[(seg + ww + 1) * 65 + ch] + r.y;
            oo.z = Of[(seg + ww + 2) * 65 + ch] + r.z;
            oo.w = Of[(seg + ww + 3) * 65 + ch] + r.w;
            *reinterpret_cast<float4*>(out + gbase + ww) = oo;
        }
    }
}

// ---------------------------------------------------------------------------
extern "C" void kernel_launch(void* const* d_in, const int* in_sizes, int n_in,
                              void* d_out, int out_size) {
    const float* A1B = (const float*)d_in[0];
    const float* A1C = (const float*)d_in[1];
    const float* w1  = (const float*)d_in[2];
    const float* b1  = (const float*)d_in[3];
    const float* w2  = (const float*)d_in[4];
    const float* b2  = (const float*)d_in[5];
    const float* w3  = (const float*)d_in[6];
    const float* b3  = (const float*)d_in[7];
    float* out = (float*)d_out;

    cudaFuncSetAttribute(conv_kernel, cudaFuncAttributeMaxDynamicSharedMemorySize, CONV_SMEM);
    cudaFuncSetAttribute(attn_kernel, cudaFuncAttributeMaxDynamicSharedMemorySize, ATTN_SMEM);

    conv_kernel<<<dim3(HW, NB), 128, CONV_SMEM>>>(A1B, A1C, w1, b1, w2, b2, w3, b3);
    attn_kernel<<<dim3(NPIX / 64, NB), 128, ATTN_SMEM>>>(A1C, out);
}

// round 14
// speedup vs baseline: 1.3656x; 1.3656x over previous
#include <cuda_runtime.h>
#include <cuda_bf16.h>
#include <cuda_fp16.h>

// ---------------------------------------------------------------------------
// BSAM self-attention via mma.sync (bf16 QK, fp16 PV), fp32 conv front.
//   Q = conv3x3(A1_B, w1*log2e, b1*log2e) -> g_Qs [b][p][hi32|lo32] bf16
//   K = conv3x3(A1_C, w2,b2)              -> g_Ks [b][p][hi32|lo32] bf16
//   V = conv3x3(A1_C, w3,b3)              -> g_V  [b][p][64] fp16
//   S = Q.K (3-way bf16 split); online per-row max softmax (base-2);
//   P fp16; O += P V. out = (O/l)^T + A1_C
// R13: standalone pack_kernel restored (R12's fused pack cost ~290 µs of
//      redundant STG); attention keeps R12's software pipeline (101 µs).
// ---------------------------------------------------------------------------

#define NB   4
#define NC   64
#define HW   64
#define NPIX 4096

typedef unsigned long long u64;
typedef unsigned u32;

__device__ __align__(16) __nv_bfloat16 g_Qs[NB * NPIX * 64];
__device__ __align__(16) __nv_bfloat16 g_Ks[NB * NPIX * 64];
__device__ __align__(16) __half        g_V [NB * NPIX * 64];
__device__ __align__(16) float g_wpack[64 * 9 * 128];
__device__ __align__(16) float g_bias[128];

// ---- packed f32x2 helpers (conv) -------------------------------------------
__device__ __forceinline__ u64 ffma2(u64 a, u64 b, u64 c) {
    u64 d; asm("fma.rn.f32x2 %0, %1, %2, %3;" : "=l"(d) : "l"(a), "l"(b), "l"(c));
    return d;
}
__device__ __forceinline__ u64 fpack2(float lo, float hi) {
    u64 d; asm("mov.b64 %0, {%1, %2};" : "=l"(d) : "f"(lo), "f"(hi));
    return d;
}
__device__ __forceinline__ float2 funpack2(u64 v) {
    float2 r; asm("mov.b64 {%0, %1}, %2;" : "=f"(r.x), "=f"(r.y) : "l"(v));
    return r;
}
__device__ __forceinline__ float ex2f(float x) {
    float y; asm("ex2.approx.f32 %0, %1;" : "=f"(y) : "f"(x));
    return y;
}

// ---- cp.async / mma / ldmatrix ----------------------------------------------
__device__ __forceinline__ void cp_async16(void* sdst, const void* gsrc) {
    u32 sa = (u32)__cvta_generic_to_shared(sdst);
    asm volatile("cp.async.cg.shared.global [%0], [%1], 16;" :: "r"(sa), "l"(gsrc));
}
#define CP_COMMIT() asm volatile("cp.async.commit_group;")
#define CP_WAIT0()  asm volatile("cp.async.wait_group 0;")
#define CP_WAIT1()  asm volatile("cp.async.wait_group 1;")

__device__ __forceinline__ void mma_bf16(float& c0, float& c1, float& c2, float& c3,
                                         u32 a0, u32 a1, u32 a2, u32 a3,
                                         u32 b0, u32 b1) {
    asm volatile(
        "mma.sync.aligned.m16n8k16.row.col.f32.bf16.bf16.f32 "
        "{%0,%1,%2,%3}, {%4,%5,%6,%7}, {%8,%9}, {%0,%1,%2,%3};"
        : "+f"(c0), "+f"(c1), "+f"(c2), "+f"(c3)
        : "r"(a0), "r"(a1), "r"(a2), "r"(a3), "r"(b0), "r"(b1));
}
__device__ __forceinline__ void mma_f16(float& c0, float& c1, float& c2, float& c3,
                                        u32 a0, u32 a1, u32 a2, u32 a3,
                                        u32 b0, u32 b1) {
    asm volatile(
        "mma.sync.aligned.m16n8k16.row.col.f32.f16.f16.f32 "
        "{%0,%1,%2,%3}, {%4,%5,%6,%7}, {%8,%9}, {%0,%1,%2,%3};"
        : "+f"(c0), "+f"(c1), "+f"(c2), "+f"(c3)
        : "r"(a0), "r"(a1), "r"(a2), "r"(a3), "r"(b0), "r"(b1));
}
__device__ __forceinline__ void ldsm4(u32* r, u32 saddr) {
    asm volatile("ldmatrix.sync.aligned.m8n8.x4.shared.b16 {%0,%1,%2,%3}, [%4];"
        : "=r"(r[0]), "=r"(r[1]), "=r"(r[2]), "=r"(r[3]) : "r"(saddr));
}
__device__ __forceinline__ void ldsm4t(u32* r, u32 saddr) {
    asm volatile("ldmatrix.sync.aligned.m8n8.x4.trans.shared.b16 {%0,%1,%2,%3}, [%4];"
        : "=r"(r[0]), "=r"(r[1]), "=r"(r[2]), "=r"(r[3]) : "r"(saddr));
}
__device__ __forceinline__ u32 h2u(__half2 h) {
    return *reinterpret_cast<u32*>(&h);
}

#define LOG2E 1.4426950408889634f

// ---------------------------------------------------------------------------
// Weight repack (standalone). co 0..31 = w1*log2e, 32..63 = w2, 64..127 = w3
// ---------------------------------------------------------------------------
__global__ void pack_kernel(const float* __restrict__ w1, const float* __restrict__ b1,
                            const float* __restrict__ w2, const float* __restrict__ b2,
                            const float* __restrict__ w3, const float* __restrict__ b3) {
    int idx = blockIdx.x * 256 + threadIdx.x;
    if (idx < 128)
        g_bias[idx] = (idx < 32) ? b1[idx] * LOG2E
                    : (idx < 64) ? b2[idx - 32] : b3[idx - 64];
    if (idx < 64 * 9 * 128) {
        int co = idx & 127;
        int t  = idx >> 7;
        int ci = t / 9;
        int k  = t % 9;
        float v;
        if (co < 32)       v = w1[(co * 64 + ci) * 9 + k] * LOG2E;
        else if (co < 64)  v = w2[((co - 32) * 64 + ci) * 9 + k];
        else               v = w3[((co - 64) * 64 + ci) * 9 + k];
        g_wpack[idx] = v;
    }
}

// ---------------------------------------------------------------------------
// Conv: block=(row y, batch b), 128 thr = 32 x-lanes x 4 groups, 2 pixels/thr.
// Q/K bf16 split [hi32|lo32]; V single fp16.
// ---------------------------------------------------------------------------
#define CONV_SMEM (2 * 64 * 3 * 66 * 4)

__global__ __launch_bounds__(128)
void conv_kernel(const float* __restrict__ A1B, const float* __restrict__ A1C) {
    extern __shared__ float smem[];
    float* sB = smem;
    float* sC = smem + 64 * 3 * 66;

    const int y   = blockIdx.x;
    const int b   = blockIdx.y;
    const int tid = threadIdx.x;

    for (int idx = tid; idx < 64 * 3 * 66; idx += 128) {
        int ci  = idx / 198;
        int rem = idx % 198;
        int r   = rem / 66;
        int xx  = rem % 66;
        int yy  = y + r - 1;
        int x   = xx - 1;
        bool ok = (yy >= 0) && (yy < HW) && (x >= 0) && (x < HW);
        float vb = 0.f, vc = 0.f;
        if (ok) {
            int gi = ((b * 64 + ci) * HW + yy) * HW + x;
            vb = __ldg(A1B + gi);
            vc = __ldg(A1C + gi);
        }
        sB[idx] = vb;
        sC[idx] = vc;
    }
    __syncthreads();

    const int x0 = tid & 31;
    const int x1 = x0 + 32;
    const int g  = tid >> 5;
    const float* sIn = (g == 0) ? sB : sC;

    #pragma unroll
    for (int pass = 0; pass < 2; ++pass) {
        const int co0 = g * 32 + pass * 16;
        const u64* bp = reinterpret_cast<const u64*>(g_bias + co0);
        u64 acc0[8], acc1[8];
        #pragma unroll
        for (int u = 0; u < 8; ++u) { acc0[u] = bp[u]; acc1[u] = bp[u]; }

        for (int ci = 0; ci < 64; ++ci) {
            #pragma unroll
            for (int dy = 0; dy < 3; ++dy) {
                const float* row = sIn + (ci * 3 + dy) * 66;
                float a0 = row[x0], a1 = row[x0 + 1], a2 = row[x0 + 2];
                float c0 = row[x1], c1 = row[x1 + 1], c2 = row[x1 + 2];
                #pragma unroll
                for (int dx = 0; dx < 3; ++dx) {
                    float ivA = (dx == 0) ? a0 : (dx == 1) ? a1 : a2;
                    float ivB = (dx == 0) ? c0 : (dx == 1) ? c1 : c2;
                    u64 iA = fpack2(ivA, ivA);
                    u64 iB = fpack2(ivB, ivB);
                    const ulonglong2* wq = reinterpret_cast<const ulonglong2*>(
                        g_wpack + ((ci * 3 + dy) * 3 + dx) * 128 + co0);
                    ulonglong2 wA = __ldg(wq + 0);
                    ulonglong2 wB = __ldg(wq + 1);
                    ulonglong2 wC = __ldg(wq + 2);
                    ulonglong2 wD = __ldg(wq + 3);
                    acc0[0] = ffma2(iA, wA.x, acc0[0]); acc1[0] = ffma2(iB, wA.x, acc1[0]);
                    acc0[1] = ffma2(iA, wA.y, acc0[1]); acc1[1] = ffma2(iB, wA.y, acc1[1]);
                    acc0[2] = ffma2(iA, wB.x, acc0[2]); acc1[2] = ffma2(iB, wB.x, acc1[2]);
                    acc0[3] = ffma2(iA, wB.y, acc0[3]); acc1[3] = ffma2(iB, wB.y, acc1[3]);
                    acc0[4] = ffma2(iA, wC.x, acc0[4]); acc1[4] = ffma2(iB, wC.x, acc1[4]);
                    acc0[5] = ffma2(iA, wC.y, acc0[5]); acc1[5] = ffma2(iB, wC.y, acc1[5]);
                    acc0[6] = ffma2(iA, wD.x, acc0[6]); acc1[6] = ffma2(iB, wD.x, acc1[6]);
                    acc0[7] = ffma2(iA, wD.y, acc0[7]); acc1[7] = ffma2(iB, wD.y, acc1[7]);
                }
            }
        }

        #pragma unroll
        for (int pix = 0; pix < 2; ++pix) {
            const u64* acc = pix ? acc1 : acc0;
            const int p = y * HW + (pix ? x1 : x0);
            if (g <= 1) {
                __nv_bfloat16* dst = (g == 0 ? g_Qs : g_Ks)
                                   + (size_t)(b * NPIX + p) * 64 + (co0 & 31);
                #pragma unroll
                for (int u = 0; u < 8; ++u) {
                    float2 v = funpack2(acc[u]);
                    __nv_bfloat162 h = __floats2bfloat162_rn(v.x, v.y);
                    __nv_bfloat162 l = __floats2bfloat162_rn(
                        v.x - __bfloat162float(h.x), v.y - __bfloat162float(h.y));
                    *reinterpret_cast<__nv_bfloat162*>(dst + 2 * u)      = h;
                    *reinterpret_cast<__nv_bfloat162*>(dst + 32 + 2 * u) = l;
                }
            } else {
                __half* dst = g_V + (size_t)(b * NPIX + p) * 64 + (co0 - 64);
                #pragma unroll
                for (int u = 0; u < 8; ++u) {
                    float2 v = funpack2(acc[u]);
                    *reinterpret_cast<__half2*>(dst + 2 * u) =
                        __floats2half2_rn(v.x, v.y);
                }
            }
        }
    }
}

// ---------------------------------------------------------------------------
// Tensor-core flash attention, software-pipelined (R12, unchanged).
// Loop body: softmax(kb) -> QK(kb+1) -> PV(kb). Triple-buffered K/V.
// SMEM rows padded to 144B: Q@0 | K0/K1/K2 @9216.. | V0/V1/V2 @36864..
// ---------------------------------------------------------------------------
#define SM_K(j) (9216 + (j) * 9216)
#define SM_V(j) (36864 + (j) * 9216)
#define ATTN_SMEM (7 * 9216)

__device__ __forceinline__ void attn_ldtile(char* dst, const char* src, int tid) {
    #pragma unroll
    for (int f = tid; f < 512; f += 128) {
        int r = f >> 3, s = (f & 7) * 16;
        cp_async16(dst + r * 144 + s, src + r * 128 + s);
    }
}

__global__ __launch_bounds__(128)
void attn_kernel(const float* __restrict__ A1C, float* __restrict__ out) {
    extern __shared__ __align__(16) char sm[];
    char* Qs  = sm;
    float* Of = reinterpret_cast<float*>(sm + 9216);

    const int rb   = blockIdx.x;
    const int b    = blockIdx.y;
    const int tid  = threadIdx.x;
    const int lane = tid & 31;
    const int w    = tid >> 5;
    const int q0   = rb * 64;
    const char* gQ = (const char*)(g_Qs + (size_t)(b * NPIX + q0) * 64);
    const char* gK = (const char*)(g_Ks + (size_t)b * NPIX * 64);
    const char* gV = (const char*)(g_V  + (size_t)b * NPIX * 64);

    // ---- prologue: group A {Q,K0,V0}, group B {K1,V1} -------------------------
    attn_ldtile(Qs, gQ, tid);
    attn_ldtile(sm + SM_K(0), gK, tid);
    attn_ldtile(sm + SM_V(0), gV, tid);
    CP_COMMIT();
    attn_ldtile(sm + SM_K(1), gK + 64 * 128, tid);
    attn_ldtile(sm + SM_V(1), gV + 64 * 128, tid);
    CP_COMMIT();
    CP_WAIT1();            // group A complete
    __syncthreads();

    // ---- Q fragments (resident for the whole kernel) --------------------------
    const u32 qrow  = w * 16 + ((lane >> 3) & 1) * 8 + (lane & 7);
    const u32 qcol8 = (lane >> 4) * 8;
    const u32 qbase = (u32)__cvta_generic_to_shared(Qs) + qrow * 144;
    u32 Ah[2][4], Al[2][4];
    ldsm4(Ah[0], qbase + (0  + qcol8) * 2);
    ldsm4(Ah[1], qbase + (16 + qcol8) * 2);
    ldsm4(Al[0], qbase + (32 + qcol8) * 2);
    ldsm4(Al[1], qbase + (48 + qcol8) * 2);

    const u32 koff = (lane & 7) * 144 + (((lane >> 3) & 1) * 8 + (lane >> 4) * 16) * 2;
    const u32 voff = (((lane >> 3) & 1) * 8 + (lane & 7)) * 144 + (lane >> 4) * 16;
    const u32 smb  = (u32)__cvta_generic_to_shared(sm);

    float o[8][4] = {};
    float lsum0 = 0.f, lsum1 = 0.f;
    float m0 = -1e30f, m1 = -1e30f;
    float c[8][4] = {};

    // ---- QK(0) -----------------------------------------------------------------
    {
        const u32 kbase = smb + SM_K(0) + koff;
        #pragma unroll
        for (int nt = 0; nt < 8; ++nt) {
            u32 bh[4], bl[4];
            u32 ra = kbase + nt * 8 * 144;
            ldsm4(bh, ra);
            ldsm4(bl, ra + 64);
            mma_bf16(c[nt][0], c[nt][1], c[nt][2], c[nt][3],
                     Ah[0][0], Ah[0][1], Ah[0][2], Ah[0][3], bh[0], bh[1]);
            mma_bf16(c[nt][0], c[nt][1], c[nt][2], c[nt][3],
                     Ah[1][0], Ah[1][1], Ah[1][2], Ah[1][3], bh[2], bh[3]);
            mma_bf16(c[nt][0], c[nt][1], c[nt][2], c[nt][3],
                     Ah[0][0], Ah[0][1], Ah[0][2], Ah[0][3], bl[0], bl[1]);
            mma_bf16(c[nt][0], c[nt][1], c[nt][2], c[nt][3],
                     Ah[1][0], Ah[1][1], Ah[1][2], Ah[1][3], bl[2], bl[3]);
            mma_bf16(c[nt][0], c[nt][1], c[nt][2], c[nt][3],
                     Al[0][0], Al[0][1], Al[0][2], Al[0][3], bh[0], bh[1]);
            mma_bf16(c[nt][0], c[nt][1], c[nt][2], c[nt][3],
                     Al[1][0], Al[1][1], Al[1][2], Al[1][3], bh[2], bh[3]);
        }
    }

    for (int kb = 0; kb < 64; ++kb) {
        const int bcur = kb % 3;
        const int bnxt = (kb + 1) % 3;
        const int bld  = (kb + 2) % 3;

        __syncthreads();   // all PV(kb-1) reads of V[bld] done before overwrite

        if (kb < 62) {
            const char* gKn = gK + (size_t)(kb + 2) * 64 * 128;
            const char* gVn = gV + (size_t)(kb + 2) * 64 * 128;
            attn_ldtile(sm + SM_K(bld), gKn, tid);
            attn_ldtile(sm + SM_V(bld), gVn, tid);
            CP_COMMIT();
        }

        // ---- online per-row max + softmax + P fp16 -----------------------------
        float mx0 = -1e30f, mx1 = -1e30f;
        #pragma unroll
        for (int nt = 0; nt < 8; ++nt) {
            mx0 = fmaxf(mx0, fmaxf(c[nt][0], c[nt][1]));
            mx1 = fmaxf(mx1, fmaxf(c[nt][2], c[nt][3]));
        }
        mx0 = fmaxf(mx0, __shfl_xor_sync(0xffffffffu, mx0, 1));
        mx0 = fmaxf(mx0, __shfl_xor_sync(0xffffffffu, mx0, 2));
        mx1 = fmaxf(mx1, __shfl_xor_sync(0xffffffffu, mx1, 1));
        mx1 = fmaxf(mx1, __shfl_xor_sync(0xffffffffu, mx1, 2));
        float mn0 = fmaxf(m0, mx0), mn1 = fmaxf(m1, mx1);
        if (mn0 > m0 || mn1 > m1) {
            float a0 = ex2f(m0 - mn0), a1 = ex2f(m1 - mn1);
            lsum0 *= a0; lsum1 *= a1;
            #pragma unroll
            for (int ct = 0; ct < 8; ++ct) {
                o[ct][0] *= a0; o[ct][1] *= a0;
                o[ct][2] *= a1; o[ct][3] *= a1;
            }
            m0 = mn0; m1 = mn1;
        }
        u32 Ph[4][4];
        #pragma unroll
        for (int nt = 0; nt < 8; ++nt) {
            float e0 = ex2f(c[nt][0] - m0);
            float e1 = ex2f(c[nt][1] - m0);
            float e2 = ex2f(c[nt][2] - m1);
            float e3 = ex2f(c[nt][3] - m1);
            lsum0 += e0 + e1;
            lsum1 += e2 + e3;
            int kt = nt >> 1, q = (nt & 1) * 2;
            Ph[kt][q]     = h2u(__floats2half2_rn(e0, e1));
            Ph[kt][q + 1] = h2u(__floats2half2_rn(e2, e3));
        }

        // ---- QK(kb+1): refill c while Ph feeds PV -------------------------------
        if (kb < 63) {
            if (kb < 62) CP_WAIT1();   // K(kb+1)'s group complete (kb+2 in flight)
            else         CP_WAIT0();   // last group drained
            __syncthreads();
            const u32 kbase = smb + SM_K(bnxt) + koff;
            #pragma unroll
            for (int nt = 0; nt < 8; ++nt) {
                u32 bh[4], bl[4];
                u32 ra = kbase + nt * 8 * 144;
                ldsm4(bh, ra);
                ldsm4(bl, ra + 64);
                float s0 = 0.f, s1 = 0.f, s2 = 0.f, s3 = 0.f;
                mma_bf16(s0, s1, s2, s3,
                         Ah[0][0], Ah[0][1], Ah[0][2], Ah[0][3], bh[0], bh[1]);
                mma_bf16(s0, s1, s2, s3,
                         Ah[1][0], Ah[1][1], Ah[1][2], Ah[1][3], bh[2], bh[3]);
                mma_bf16(s0, s1, s2, s3,
                         Ah[0][0], Ah[0][1], Ah[0][2], Ah[0][3], bl[0], bl[1]);
                mma_bf16(s0, s1, s2, s3,
                         Ah[1][0], Ah[1][1], Ah[1][2], Ah[1][3], bl[2], bl[3]);
                mma_bf16(s0, s1, s2, s3,
                         Al[0][0], Al[0][1], Al[0][2], Al[0][3], bh[0], bh[1]);
                mma_bf16(s0, s1, s2, s3,
                         Al[1][0], Al[1][1], Al[1][2], Al[1][3], bh[2], bh[3]);
                c[nt][0] = s0; c[nt][1] = s1; c[nt][2] = s2; c[nt][3] = s3;
            }
        }

        // ---- PV(kb) --------------------------------------------------------------
        const u32 vbase = smb + SM_V(bcur) + voff;
        #pragma unroll
        for (int kt = 0; kt < 4; ++kt) {
            #pragma unroll
            for (int cb = 0; cb < 4; ++cb) {
                u32 vr[4];
                ldsm4t(vr, vbase + kt * 16 * 144 + cb * 32);
                float* oa = o[2 * cb];
                float* ob = o[2 * cb + 1];
                mma_f16(oa[0], oa[1], oa[2], oa[3],
                        Ph[kt][0], Ph[kt][1], Ph[kt][2], Ph[kt][3], vr[0], vr[1]);
                mma_f16(ob[0], ob[1], ob[2], ob[3],
                        Ph[kt][0], Ph[kt][1], Ph[kt][2], Ph[kt][3], vr[2], vr[3]);
            }
        }
    }

    // ---- l reduction across the quad ------------------------------------------
    lsum0 += __shfl_xor_sync(0xffffffffu, lsum0, 1);
    lsum0 += __shfl_xor_sync(0xffffffffu, lsum0, 2);
    lsum1 += __shfl_xor_sync(0xffffffffu, lsum1, 1);
    lsum1 += __shfl_xor_sync(0xffffffffu, lsum1, 2);

    __syncthreads();   // all PV reads done before Of overlays the K region

    // ---- stage O/l into SMEM [row][ch] (stride 65) -------------------------------
    {
        float inv0 = 1.f / lsum0, inv1 = 1.f / lsum1;
        int r0 = w * 16 + (lane >> 2);
        int cc = (lane & 3) * 2;
        #pragma unroll
        for (int ct = 0; ct < 8; ++ct) {
            Of[r0 * 65 + ct * 8 + cc]           = o[ct][0] * inv0;
            Of[r0 * 65 + ct * 8 + cc + 1]       = o[ct][1] * inv0;
            Of[(r0 + 8) * 65 + ct * 8 + cc]     = o[ct][2] * inv1;
            Of[(r0 + 8) * 65 + ct * 8 + cc + 1] = o[ct][3] * inv1;
        }
    }
    __syncthreads();

    // ---- coalesced transpose-out + residual ---------------------------------------
    {
        int ch = tid >> 1, seg = (tid & 1) * 32;
        int gbase = (b * 64 + ch) * NPIX + q0 + seg;
        #pragma unroll
        for (int ww = 0; ww < 32; ww += 4) {
            float4 r = *reinterpret_cast<const float4*>(A1C + gbase + ww);
            float4 oo;
            oo.x = Of[(seg + ww + 0) * 65 + ch] + r.x;
            oo.y = Of[(seg + ww + 1) * 65 + ch] + r.y;
            oo.z = Of[(seg + ww + 2) * 65 + ch] + r.z;
            oo.w = Of[(seg + ww + 3) * 65 + ch] + r.w;
            *reinterpret_cast<float4*>(out + gbase + ww) = oo;
        }
    }
}

// ---------------------------------------------------------------------------
extern "C" void kernel_launch(void* const* d_in, const int* in_sizes, int n_in,
                              void* d_out, int out_size) {
    const float* A1B = (const float*)d_in[0];
    const float* A1C = (const float*)d_in[1];
    const float* w1  = (const float*)d_in[2];
    const float* b1  = (const float*)d_in[3];
    const float* w2  = (const float*)d_in[4];
    const float* b2  = (const float*)d_in[5];
    const float* w3  = (const float*)d_in[6];
    const float* b3  = (const float*)d_in[7];
    float* out = (float*)d_out;

    cudaFuncSetAttribute(conv_kernel, cudaFuncAttributeMaxDynamicSharedMemorySize, CONV_SMEM);
    cudaFuncSetAttribute(attn_kernel, cudaFuncAttributeMaxDynamicSharedMemorySize, ATTN_SMEM);

    pack_kernel<<<288, 256>>>(w1, b1, w2, b2, w3, b3);
    conv_kernel<<<dim3(HW, NB), 128, CONV_SMEM>>>(A1B, A1C);
    attn_kernel<<<dim3(NPIX / 64, NB), 128, ATTN_SMEM>>>(A1C, out);
}

// round 15
// speedup vs baseline: 2.3104x; 1.6918x over previous
#include <cuda_runtime.h>
#include <cuda_bf16.h>
#include <cuda_fp16.h>

// ---------------------------------------------------------------------------
// BSAM self-attention via mma.sync (bf16 QK, fp16 PV), fp32 conv front.
//   Q = conv3x3(A1_B, w1*log2e, b1*log2e) -> g_Qs [b][p][hi32|lo32] bf16
//   K = conv3x3(A1_C, w2,b2)              -> g_Ks [b][p][hi32|lo32] bf16
//   V = conv3x3(A1_C, w3,b3)              -> g_V  [b][p][64] fp16
// R14: conv restructured — block=(4 rows, batch, co-group); weight slice
//      (73.7 KB) cached in SMEM (kills the 235 µs L2-latency conv).
//      Attention reverted to R11 (simple loop, ~90 µs).
// ---------------------------------------------------------------------------

#define NB   4
#define NC   64
#define HW   64
#define NPIX 4096

typedef unsigned long long u64;
typedef unsigned u32;

__device__ __align__(16) __nv_bfloat16 g_Qs[NB * NPIX * 64];
__device__ __align__(16) __nv_bfloat16 g_Ks[NB * NPIX * 64];
__device__ __align__(16) __half        g_V [NB * NPIX * 64];
__device__ __align__(16) float g_wpack[64 * 9 * 128];
__device__ __align__(16) float g_bias[128];

// ---- packed f32x2 helpers (conv) -------------------------------------------
__device__ __forceinline__ u64 ffma2(u64 a, u64 b, u64 c) {
    u64 d; asm("fma.rn.f32x2 %0, %1, %2, %3;" : "=l"(d) : "l"(a), "l"(b), "l"(c));
    return d;
}
__device__ __forceinline__ u64 fpack2(float lo, float hi) {
    u64 d; asm("mov.b64 %0, {%1, %2};" : "=l"(d) : "f"(lo), "f"(hi));
    return d;
}
__device__ __forceinline__ float2 funpack2(u64 v) {
    float2 r; asm("mov.b64 {%0, %1}, %2;" : "=f"(r.x), "=f"(r.y) : "l"(v));
    return r;
}
__device__ __forceinline__ float ex2f(float x) {
    float y; asm("ex2.approx.f32 %0, %1;" : "=f"(y) : "f"(x));
    return y;
}

// ---- cp.async / mma / ldmatrix ----------------------------------------------
__device__ __forceinline__ void cp_async16(void* sdst, const void* gsrc) {
    u32 sa = (u32)__cvta_generic_to_shared(sdst);
    asm volatile("cp.async.cg.shared.global [%0], [%1], 16;" :: "r"(sa), "l"(gsrc));
}
#define CP_COMMIT() asm volatile("cp.async.commit_group;")
#define CP_WAIT0()  asm volatile("cp.async.wait_group 0;")

__device__ __forceinline__ void mma_bf16(float& c0, float& c1, float& c2, float& c3,
                                         u32 a0, u32 a1, u32 a2, u32 a3,
                                         u32 b0, u32 b1) {
    asm volatile(
        "mma.sync.aligned.m16n8k16.row.col.f32.bf16.bf16.f32 "
        "{%0,%1,%2,%3}, {%4,%5,%6,%7}, {%8,%9}, {%0,%1,%2,%3};"
        : "+f"(c0), "+f"(c1), "+f"(c2), "+f"(c3)
        : "r"(a0), "r"(a1), "r"(a2), "r"(a3), "r"(b0), "r"(b1));
}
__device__ __forceinline__ void mma_f16(float& c0, float& c1, float& c2, float& c3,
                                        u32 a0, u32 a1, u32 a2, u32 a3,
                                        u32 b0, u32 b1) {
    asm volatile(
        "mma.sync.aligned.m16n8k16.row.col.f32.f16.f16.f32 "
        "{%0,%1,%2,%3}, {%4,%5,%6,%7}, {%8,%9}, {%0,%1,%2,%3};"
        : "+f"(c0), "+f"(c1), "+f"(c2), "+f"(c3)
        : "r"(a0), "r"(a1), "r"(a2), "r"(a3), "r"(b0), "r"(b1));
}
__device__ __forceinline__ void ldsm4(u32* r, u32 saddr) {
    asm volatile("ldmatrix.sync.aligned.m8n8.x4.shared.b16 {%0,%1,%2,%3}, [%4];"
        : "=r"(r[0]), "=r"(r[1]), "=r"(r[2]), "=r"(r[3]) : "r"(saddr));
}
__device__ __forceinline__ void ldsm4t(u32* r, u32 saddr) {
    asm volatile("ldmatrix.sync.aligned.m8n8.x4.trans.shared.b16 {%0,%1,%2,%3}, [%4];"
        : "=r"(r[0]), "=r"(r[1]), "=r"(r[2]), "=r"(r[3]) : "r"(saddr));
}
__device__ __forceinline__ u32 h2u(__half2 h) {
    return *reinterpret_cast<u32*>(&h);
}

#define LOG2E 1.4426950408889634f

// ---------------------------------------------------------------------------
// Weight repack. co 0..31 = w1*log2e (Q), 32..63 = w2, 64..127 = w3
// ---------------------------------------------------------------------------
__global__ void pack_kernel(const float* __restrict__ w1, const float* __restrict__ b1,
                            const float* __restrict__ w2, const float* __restrict__ b2,
                            const float* __restrict__ w3, const float* __restrict__ b3) {
    int idx = blockIdx.x * 256 + threadIdx.x;
    if (idx < 128)
        g_bias[idx] = (idx < 32) ? b1[idx] * LOG2E
                    : (idx < 64) ? b2[idx - 32] : b3[idx - 64];
    if (idx < 64 * 9 * 128) {
        int co = idx & 127;
        int t  = idx >> 7;
        int ci = t / 9;
        int k  = t % 9;
        float v;
        if (co < 32)       v = w1[(co * 64 + ci) * 9 + k] * LOG2E;
        else if (co < 64)  v = w2[((co - 32) * 64 + ci) * 9 + k];
        else               v = w3[((co - 64) * 64 + ci) * 9 + k];
        g_wpack[idx] = v;
    }
}

// ---------------------------------------------------------------------------
// Conv: block = (4-row group, batch, co-group g). 256 thr = 4 ty x 64 x.
// SMEM: sIn[64ci][6r][66xx] (101 KB) + sW[576][32co] (73.7 KB) = 175 KB.
// Thread: 1 pixel x 32 output channels (16 f32x2 accumulators).
// g=0 -> Q (input B), g=1 -> K, g=2/3 -> V co 0..31 / 32..63 (input C).
// Accumulation order per output identical to R13 -> bitwise-same Q/K/V.
// ---------------------------------------------------------------------------
#define CONV_SMEM ((64 * 6 * 66 + 576 * 32) * 4)

__global__ __launch_bounds__(256)
void conv_kernel(const float* __restrict__ A1B, const float* __restrict__ A1C) {
    extern __shared__ float smem[];
    float* sIn = smem;               // [64][6][66]
    float* sW  = smem + 64 * 6 * 66; // [576][32]

    const int y0  = blockIdx.x * 4;
    const int b   = blockIdx.y;
    const int g   = blockIdx.z;
    const int tid = threadIdx.x;
    const float* src = (g == 0) ? A1B : A1C;

    // stage this group's weight slice: [t 0..575][co 0..31], coalesced
    for (int idx = tid; idx < 576 * 32; idx += 256) {
        int t = idx >> 5, co = idx & 31;
        sW[idx] = __ldg(g_wpack + t * 128 + g * 32 + co);
    }
    // stage 6 input rows x 64 ch (x-padded to 66)
    for (int idx = tid; idx < 64 * 6 * 66; idx += 256) {
        int ci  = idx / 396;
        int rem = idx % 396;
        int r   = rem / 66;
        int xx  = rem % 66;
        int yy  = y0 + r - 1;
        int x   = xx - 1;
        float v = 0.f;
        if (yy >= 0 && yy < HW && x >= 0 && x < HW)
            v = __ldg(src + ((size_t)(b * 64 + ci) * HW + yy) * HW + x);
        sIn[idx] = v;
    }
    __syncthreads();

    const int x  = tid & 63;
    const int ty = tid >> 6;

    u64 acc[16];
    {
        const u64* bp = reinterpret_cast<const u64*>(g_bias + g * 32);
        #pragma unroll
        for (int u = 0; u < 16; ++u) acc[u] = __ldg(bp + u);
    }

    for (int ci = 0; ci < 64; ++ci) {
        #pragma unroll
        for (int dy = 0; dy < 3; ++dy) {
            const float* row = sIn + ci * 396 + (ty + dy) * 66;
            float i0 = row[x], i1 = row[x + 1], i2 = row[x + 2];
            #pragma unroll
            for (int dx = 0; dx < 3; ++dx) {
                float iv = (dx == 0) ? i0 : (dx == 1) ? i1 : i2;
                u64 ip = fpack2(iv, iv);
                const ulonglong2* wr = reinterpret_cast<const ulonglong2*>(
                    sW + ((ci * 3 + dy) * 3 + dx) * 32);
                ulonglong2 wA = wr[0];
                ulonglong2 wB = wr[1];
                ulonglong2 wC = wr[2];
                ulonglong2 wD = wr[3];
                acc[0]  = ffma2(ip, wA.x, acc[0]);
                acc[1]  = ffma2(ip, wA.y, acc[1]);
                acc[2]  = ffma2(ip, wB.x, acc[2]);
                acc[3]  = ffma2(ip, wB.y, acc[3]);
                acc[4]  = ffma2(ip, wC.x, acc[4]);
                acc[5]  = ffma2(ip, wC.y, acc[5]);
                acc[6]  = ffma2(ip, wD.x, acc[6]);
                acc[7]  = ffma2(ip, wD.y, acc[7]);
                const ulonglong2* wr2 = wr + 4;
                ulonglong2 wE = wr2[0];
                ulonglong2 wF = wr2[1];
                ulonglong2 wG = wr2[2];
                ulonglong2 wH = wr2[3];
                acc[8]  = ffma2(ip, wE.x, acc[8]);
                acc[9]  = ffma2(ip, wE.y, acc[9]);
                acc[10] = ffma2(ip, wF.x, acc[10]);
                acc[11] = ffma2(ip, wF.y, acc[11]);
                acc[12] = ffma2(ip, wG.x, acc[12]);
                acc[13] = ffma2(ip, wG.y, acc[13]);
                acc[14] = ffma2(ip, wH.x, acc[14]);
                acc[15] = ffma2(ip, wH.y, acc[15]);
            }
        }
    }

    // write out: p = (y0+ty)*64 + x
    const int p = (y0 + ty) * HW + x;
    if (g <= 1) {
        __nv_bfloat16* dst = (g == 0 ? g_Qs : g_Ks) + (size_t)(b * NPIX + p) * 64;
        #pragma unroll
        for (int u = 0; u < 16; ++u) {
            float2 v = funpack2(acc[u]);
            __nv_bfloat162 h = __floats2bfloat162_rn(v.x, v.y);
            __nv_bfloat162 l = __floats2bfloat162_rn(
                v.x - __bfloat162float(h.x), v.y - __bfloat162float(h.y));
            *reinterpret_cast<__nv_bfloat162*>(dst + 2 * u)      = h;
            *reinterpret_cast<__nv_bfloat162*>(dst + 32 + 2 * u) = l;
        }
    } else {
        __half* dst = g_V + (size_t)(b * NPIX + p) * 64 + (g - 2) * 32;
        #pragma unroll
        for (int u = 0; u < 16; ++u) {
            float2 v = funpack2(acc[u]);
            *reinterpret_cast<__half2*>(dst + 2 * u) = __floats2half2_rn(v.x, v.y);
        }
    }
}

// ---------------------------------------------------------------------------
// Tensor-core flash attention (R11, the 329.8 µs version — unchanged).
// 128 thr = 4 warps; online per-row max softmax; P fp16; V fp16.
// SMEM rows padded to 144B: Qs@0 | K0@9216 K1@18432 | V0@27648 V1@36864
// ---------------------------------------------------------------------------
#define ATTN_SMEM (5 * 9216)

__global__ __launch_bounds__(128)
void attn_kernel(const float* __restrict__ A1C, float* __restrict__ out) {
    extern __shared__ __align__(16) char sm[];
    char* Qs  = sm;
    char* Kb0 = sm + 9216;
    char* Vb0 = sm + 27648;
    float* Of = reinterpret_cast<float*>(sm + 9216);

    const int rb   = blockIdx.x;
    const int b    = blockIdx.y;
    const int tid  = threadIdx.x;
    const int lane = tid & 31;
    const int w    = tid >> 5;
    const int q0   = rb * 64;
    const char* gQ = (const char*)(g_Qs + (size_t)(b * NPIX + q0) * 64);
    const char* gK = (const char*)(g_Ks + (size_t)b * NPIX * 64);
    const char* gV = (const char*)(g_V  + (size_t)b * NPIX * 64);

    for (int f = tid; f < 512; f += 128) {
        int r = f >> 3, s = (f & 7) * 16;
        cp_async16(Qs  + r * 144 + s, gQ + r * 128 + s);
        cp_async16(Kb0 + r * 144 + s, gK + r * 128 + s);
        cp_async16(Vb0 + r * 144 + s, gV + r * 128 + s);
    }
    CP_COMMIT();
    CP_WAIT0();
    __syncthreads();

    const u32 qrow  = w * 16 + ((lane >> 3) & 1) * 8 + (lane & 7);
    const u32 qcol8 = (lane >> 4) * 8;
    const u32 qbase = (u32)__cvta_generic_to_shared(Qs) + qrow * 144;
    u32 Ah[2][4], Al[2][4];
    ldsm4(Ah[0], qbase + (0  + qcol8) * 2);
    ldsm4(Ah[1], qbase + (16 + qcol8) * 2);
    ldsm4(Al[0], qbase + (32 + qcol8) * 2);
    ldsm4(Al[1], qbase + (48 + qcol8) * 2);

    const u32 koff = (lane & 7) * 144 + (((lane >> 3) & 1) * 8 + (lane >> 4) * 16) * 2;
    const u32 voff = (((lane >> 3) & 1) * 8 + (lane & 7)) * 144 + (lane >> 4) * 16;

    float o[8][4] = {};
    float lsum0 = 0.f, lsum1 = 0.f;
    float m0 = -1e30f, m1 = -1e30f;

    for (int kb = 0; kb < 64; ++kb) {
        const int buf = kb & 1;
        if (kb > 0) {
            CP_WAIT0();
            __syncthreads();
        }
        if (kb < 63) {
            const char* gKn = gK + (size_t)(kb + 1) * 64 * 128;
            const char* gVn = gV + (size_t)(kb + 1) * 64 * 128;
            char* Kn = Kb0 + (buf ^ 1) * 9216;
            char* Vn = Vb0 + (buf ^ 1) * 9216;
            for (int f = tid; f < 512; f += 128) {
                int r = f >> 3, s = (f & 7) * 16;
                cp_async16(Kn + r * 144 + s, gKn + r * 128 + s);
                cp_async16(Vn + r * 144 + s, gVn + r * 128 + s);
            }
        }
        CP_COMMIT();

        const u32 kbase = (u32)__cvta_generic_to_shared(Kb0 + buf * 9216) + koff;
        float c[8][4] = {};
        #pragma unroll
        for (int nt = 0; nt < 8; ++nt) {
            u32 bh[4], bl[4];
            u32 ra = kbase + nt * 8 * 144;
            ldsm4(bh, ra);
            ldsm4(bl, ra + 64);
            mma_bf16(c[nt][0], c[nt][1], c[nt][2], c[nt][3],
                     Ah[0][0], Ah[0][1], Ah[0][2], Ah[0][3], bh[0], bh[1]);
            mma_bf16(c[nt][0], c[nt][1], c[nt][2], c[nt][3],
                     Ah[1][0], Ah[1][1], Ah[1][2], Ah[1][3], bh[2], bh[3]);
            mma_bf16(c[nt][0], c[nt][1], c[nt][2], c[nt][3],
                     Ah[0][0], Ah[0][1], Ah[0][2], Ah[0][3], bl[0], bl[1]);
            mma_bf16(c[nt][0], c[nt][1], c[nt][2], c[nt][3],
                     Ah[1][0], Ah[1][1], Ah[1][2], Ah[1][3], bl[2], bl[3]);
            mma_bf16(c[nt][0], c[nt][1], c[nt][2], c[nt][3],
                     Al[0][0], Al[0][1], Al[0][2], Al[0][3], bh[0], bh[1]);
            mma_bf16(c[nt][0], c[nt][1], c[nt][2], c[nt][3],
                     Al[1][0], Al[1][1], Al[1][2], Al[1][3], bh[2], bh[3]);
        }

        float mx0 = -1e30f, mx1 = -1e30f;
        #pragma unroll
        for (int nt = 0; nt < 8; ++nt) {
            mx0 = fmaxf(mx0, fmaxf(c[nt][0], c[nt][1]));
            mx1 = fmaxf(mx1, fmaxf(c[nt][2], c[nt][3]));
        }
        mx0 = fmaxf(mx0, __shfl_xor_sync(0xffffffffu, mx0, 1));
        mx0 = fmaxf(mx0, __shfl_xor_sync(0xffffffffu, mx0, 2));
        mx1 = fmaxf(mx1, __shfl_xor_sync(0xffffffffu, mx1, 1));
        mx1 = fmaxf(mx1, __shfl_xor_sync(0xffffffffu, mx1, 2));
        float mn0 = fmaxf(m0, mx0), mn1 = fmaxf(m1, mx1);
        if (mn0 > m0 || mn1 > m1) {
            float a0 = ex2f(m0 - mn0), a1 = ex2f(m1 - mn1);
            lsum0 *= a0; lsum1 *= a1;
            #pragma unroll
            for (int ct = 0; ct < 8; ++ct) {
                o[ct][0] *= a0; o[ct][1] *= a0;
                o[ct][2] *= a1; o[ct][3] *= a1;
            }
            m0 = mn0; m1 = mn1;
        }
        u32 Ph[4][4];
        #pragma unroll
        for (int nt = 0; nt < 8; ++nt) {
            float e0 = ex2f(c[nt][0] - m0);
            float e1 = ex2f(c[nt][1] - m0);
            float e2 = ex2f(c[nt][2] - m1);
            float e3 = ex2f(c[nt][3] - m1);
            lsum0 += e0 + e1;
            lsum1 += e2 + e3;
            int kt = nt >> 1, q = (nt & 1) * 2;
            Ph[kt][q]     = h2u(__floats2half2_rn(e0, e1));
            Ph[kt][q + 1] = h2u(__floats2half2_rn(e2, e3));
        }

        const u32 vbase = (u32)__cvta_generic_to_shared(Vb0 + buf * 9216) + voff;
        #pragma unroll
        for (int kt = 0; kt < 4; ++kt) {
            #pragma unroll
            for (int cb = 0; cb < 4; ++cb) {
                u32 vr[4];
                ldsm4t(vr, vbase + kt * 16 * 144 + cb * 32);
                float* oa = o[2 * cb];
                float* ob = o[2 * cb + 1];
                mma_f16(oa[0], oa[1], oa[2], oa[3],
                        Ph[kt][0], Ph[kt][1], Ph[kt][2], Ph[kt][3], vr[0], vr[1]);
                mma_f16(ob[0], ob[1], ob[2], ob[3],
                        Ph[kt][0], Ph[kt][1], Ph[kt][2], Ph[kt][3], vr[2], vr[3]);
            }
        }
    }

    lsum0 += __shfl_xor_sync(0xffffffffu, lsum0, 1);
    lsum0 += __shfl_xor_sync(0xffffffffu, lsum0, 2);
    lsum1 += __shfl_xor_sync(0xffffffffu, lsum1, 1);
    lsum1 += __shfl_xor_sync(0xffffffffu, lsum1, 2);

    __syncthreads();

    {
        float inv0 = 1.f / lsum0, inv1 = 1.f / lsum1;
        int r0 = w * 16 + (lane >> 2);
        int cc = (lane & 3) * 2;
        #pragma unroll
        for (int ct = 0; ct < 8; ++ct) {
            Of[r0 * 65 + ct * 8 + cc]           = o[ct][0] * inv0;
            Of[r0 * 65 + ct * 8 + cc + 1]       = o[ct][1] * inv0;
            Of[(r0 + 8) * 65 + ct * 8 + cc]     = o[ct][2] * inv1;
            Of[(r0 + 8) * 65 + ct * 8 + cc + 1] = o[ct][3] * inv1;
        }
    }
    __syncthreads();

    {
        int ch = tid >> 1, seg = (tid & 1) * 32;
        int gbase = (b * 64 + ch) * NPIX + q0 + seg;
        #pragma unroll
        for (int ww = 0; ww < 32; ww += 4) {
            float4 r = *reinterpret_cast<const float4*>(A1C + gbase + ww);
            float4 oo;
            oo.x = Of[(seg + ww + 0) * 65 + ch] + r.x;
            oo.y = Of[(seg + ww + 1) * 65 + ch] + r.y;
            oo.z = Of[(seg + ww + 2) * 65 + ch] + r.z;
            oo.w = Of[(seg + ww + 3) * 65 + ch] + r.w;
            *reinterpret_cast<float4*>(out + gbase + ww) = oo;
        }
    }
}

// ---------------------------------------------------------------------------
extern "C" void kernel_launch(void* const* d_in, const int* in_sizes, int n_in,
                              void* d_out, int out_size) {
    const float* A1B = (const float*)d_in[0];
    const float* A1C = (const float*)d_in[1];
    const float* w1  = (const float*)d_in[2];
    const float* b1  = (const float*)d_in[3];
    const float* w2  = (const float*)d_in[4];
    const float* b2  = (const float*)d_in[5];
    const float* w3  = (const float*)d_in[6];
    const float* b3  = (const float*)d_in[7];
    float* out = (float*)d_out;

    cudaFuncSetAttribute(conv_kernel, cudaFuncAttributeMaxDynamicSharedMemorySize, CONV_SMEM);
    cudaFuncSetAttribute(attn_kernel, cudaFuncAttributeMaxDynamicSharedMemorySize, ATTN_SMEM);

    pack_kernel<<<288, 256>>>(w1, b1, w2, b2, w3, b3);
    conv_kernel<<<dim3(16, NB, 4), 256, CONV_SMEM>>>(A1B, A1C);
    attn_kernel<<<dim3(NPIX / 64, NB), 128, ATTN_SMEM>>>(A1C, out);
}

// round 16
// speedup vs baseline: 2.3341x; 1.0103x over previous
#include <cuda_runtime.h>
#include <cuda_bf16.h>
#include <cuda_fp16.h>

// ---------------------------------------------------------------------------
// BSAM self-attention via mma.sync (bf16 QK, fp16 PV), fp32 conv front.
// R15: conv single-wave — 128 blocks (8 rows x batch x group), 2 pixels/thr,
//      input staged in two ci-halves (84.5 KB) + full weight slice (73.7 KB).
//      Attention = R11/R14 version (unchanged).
// ---------------------------------------------------------------------------

#define NB   4
#define NC   64
#define HW   64
#define NPIX 4096

typedef unsigned long long u64;
typedef unsigned u32;

__device__ __align__(16) __nv_bfloat16 g_Qs[NB * NPIX * 64];
__device__ __align__(16) __nv_bfloat16 g_Ks[NB * NPIX * 64];
__device__ __align__(16) __half        g_V [NB * NPIX * 64];
__device__ __align__(16) float g_wpack[64 * 9 * 128];
__device__ __align__(16) float g_bias[128];

// ---- packed f32x2 helpers (conv) -------------------------------------------
__device__ __forceinline__ u64 ffma2(u64 a, u64 b, u64 c) {
    u64 d; asm("fma.rn.f32x2 %0, %1, %2, %3;" : "=l"(d) : "l"(a), "l"(b), "l"(c));
    return d;
}
__device__ __forceinline__ u64 fpack2(float lo, float hi) {
    u64 d; asm("mov.b64 %0, {%1, %2};" : "=l"(d) : "f"(lo), "f"(hi));
    return d;
}
__device__ __forceinline__ float2 funpack2(u64 v) {
    float2 r; asm("mov.b64 {%0, %1}, %2;" : "=f"(r.x), "=f"(r.y) : "l"(v));
    return r;
}
__device__ __forceinline__ float ex2f(float x) {
    float y; asm("ex2.approx.f32 %0, %1;" : "=f"(y) : "f"(x));
    return y;
}

// ---- cp.async / mma / ldmatrix ----------------------------------------------
__device__ __forceinline__ void cp_async16(void* sdst, const void* gsrc) {
    u32 sa = (u32)__cvta_generic_to_shared(sdst);
    asm volatile("cp.async.cg.shared.global [%0], [%1], 16;" :: "r"(sa), "l"(gsrc));
}
#define CP_COMMIT() asm volatile("cp.async.commit_group;")
#define CP_WAIT0()  asm volatile("cp.async.wait_group 0;")

__device__ __forceinline__ void mma_bf16(float& c0, float& c1, float& c2, float& c3,
                                         u32 a0, u32 a1, u32 a2, u32 a3,
                                         u32 b0, u32 b1) {
    asm volatile(
        "mma.sync.aligned.m16n8k16.row.col.f32.bf16.bf16.f32 "
        "{%0,%1,%2,%3}, {%4,%5,%6,%7}, {%8,%9}, {%0,%1,%2,%3};"
        : "+f"(c0), "+f"(c1), "+f"(c2), "+f"(c3)
        : "r"(a0), "r"(a1), "r"(a2), "r"(a3), "r"(b0), "r"(b1));
}
__device__ __forceinline__ void mma_f16(float& c0, float& c1, float& c2, float& c3,
                                        u32 a0, u32 a1, u32 a2, u32 a3,
                                        u32 b0, u32 b1) {
    asm volatile(
        "mma.sync.aligned.m16n8k16.row.col.f32.f16.f16.f32 "
        "{%0,%1,%2,%3}, {%4,%5,%6,%7}, {%8,%9}, {%0,%1,%2,%3};"
        : "+f"(c0), "+f"(c1), "+f"(c2), "+f"(c3)
        : "r"(a0), "r"(a1), "r"(a2), "r"(a3), "r"(b0), "r"(b1));
}
__device__ __forceinline__ void ldsm4(u32* r, u32 saddr) {
    asm volatile("ldmatrix.sync.aligned.m8n8.x4.shared.b16 {%0,%1,%2,%3}, [%4];"
        : "=r"(r[0]), "=r"(r[1]), "=r"(r[2]), "=r"(r[3]) : "r"(saddr));
}
__device__ __forceinline__ void ldsm4t(u32* r, u32 saddr) {
    asm volatile("ldmatrix.sync.aligned.m8n8.x4.trans.shared.b16 {%0,%1,%2,%3}, [%4];"
        : "=r"(r[0]), "=r"(r[1]), "=r"(r[2]), "=r"(r[3]) : "r"(saddr));
}
__device__ __forceinline__ u32 h2u(__half2 h) {
    return *reinterpret_cast<u32*>(&h);
}

#define LOG2E 1.4426950408889634f

// ---------------------------------------------------------------------------
// Weight repack. co 0..31 = w1*log2e (Q), 32..63 = w2, 64..127 = w3
// ---------------------------------------------------------------------------
__global__ void pack_kernel(const float* __restrict__ w1, const float* __restrict__ b1,
                            const float* __restrict__ w2, const float* __restrict__ b2,
                            const float* __restrict__ w3, const float* __restrict__ b3) {
    int idx = blockIdx.x * 256 + threadIdx.x;
    if (idx < 128)
        g_bias[idx] = (idx < 32) ? b1[idx] * LOG2E
                    : (idx < 64) ? b2[idx - 32] : b3[idx - 64];
    if (idx < 64 * 9 * 128) {
        int co = idx & 127;
        int t  = idx >> 7;
        int ci = t / 9;
        int k  = t % 9;
        float v;
        if (co < 32)       v = w1[(co * 64 + ci) * 9 + k] * LOG2E;
        else if (co < 64)  v = w2[((co - 32) * 64 + ci) * 9 + k];
        else               v = w3[((co - 64) * 64 + ci) * 9 + k];
        g_wpack[idx] = v;
    }
}

// ---------------------------------------------------------------------------
// Conv: block = (8-row group, batch, co-group g); 128 blocks = single wave.
// 256 thr = 64x * 4ty; thread computes rows (y0+ty, y0+ty+4) x 32 co.
// SMEM: sIn[32ci][10r][66xx] (84.5 KB, restaged per ci-half) + sW[576][32].
// Accumulation order per output identical to R14 -> bitwise-same Q/K/V.
// ---------------------------------------------------------------------------
#define CONV_SIN  (32 * 10 * 66)
#define CONV_SMEM ((CONV_SIN + 576 * 32) * 4)

__global__ __launch_bounds__(256)
void conv_kernel(const float* __restrict__ A1B, const float* __restrict__ A1C) {
    extern __shared__ float smem[];
    float* sIn = smem;               // [32][10][66]
    float* sW  = smem + CONV_SIN;    // [576][32]

    const int y0  = blockIdx.x * 8;
    const int b   = blockIdx.y;
    const int g   = blockIdx.z;
    const int tid = threadIdx.x;
    const float* src = (g == 0) ? A1B : A1C;

    // stage full weight slice: [t 0..575][co 0..31]
    for (int idx = tid; idx < 576 * 32; idx += 256) {
        int t = idx >> 5, co = idx & 31;
        sW[idx] = __ldg(g_wpack + t * 128 + g * 32 + co);
    }

    const int x  = tid & 63;
    const int ty = tid >> 6;

    u64 accA[16], accB[16];
    {
        const u64* bp = reinterpret_cast<const u64*>(g_bias + g * 32);
        #pragma unroll
        for (int u = 0; u < 16; ++u) { accA[u] = __ldg(bp + u); accB[u] = accA[u]; }
    }

    for (int h = 0; h < 2; ++h) {
        // stage ci-half h: 32 ci x 10 rows x 66 (zero-padded boundaries)
        __syncthreads();   // (h=1: all reads of previous half done)
        for (int idx = tid; idx < CONV_SIN; idx += 256) {
            int ci  = idx / 660;
            int rem = idx % 660;
            int r   = rem / 66;
            int xx  = rem % 66;
            int yy  = y0 + r - 1;
            int xi  = xx - 1;
            float v = 0.f;
            if (yy >= 0 && yy < HW && xi >= 0 && xi < HW)
                v = __ldg(src + ((size_t)(b * 64 + h * 32 + ci) * HW + yy) * HW + xi);
            sIn[idx] = v;
        }
        __syncthreads();

        for (int ci = 0; ci < 32; ++ci) {
            #pragma unroll
            for (int dy = 0; dy < 3; ++dy) {
                const float* rowA = sIn + ci * 660 + (ty + dy) * 66;
                const float* rowB = rowA + 4 * 66;
                float a0 = rowA[x], a1 = rowA[x + 1], a2 = rowA[x + 2];
                float b0 = rowB[x], b1 = rowB[x + 1], b2 = rowB[x + 2];
                const int tbase = ((h * 32 + ci) * 3 + dy) * 3;
                #pragma unroll
                for (int dx = 0; dx < 3; ++dx) {
                    float ivA = (dx == 0) ? a0 : (dx == 1) ? a1 : a2;
                    float ivB = (dx == 0) ? b0 : (dx == 1) ? b1 : b2;
                    u64 ipA = fpack2(ivA, ivA);
                    u64 ipB = fpack2(ivB, ivB);
                    const ulonglong2* wr = reinterpret_cast<const ulonglong2*>(
                        sW + (tbase + dx) * 32);
                    #pragma unroll
                    for (int q = 0; q < 4; ++q) {
                        ulonglong2 wv = wr[q];
                        accA[2 * q]     = ffma2(ipA, wv.x, accA[2 * q]);
                        accA[2 * q + 1] = ffma2(ipA, wv.y, accA[2 * q + 1]);
                        accB[2 * q]     = ffma2(ipB, wv.x, accB[2 * q]);
                        accB[2 * q + 1] = ffma2(ipB, wv.y, accB[2 * q + 1]);
                    }
                    #pragma unroll
                    for (int q = 4; q < 8; ++q) {
                        ulonglong2 wv = wr[q];
                        accA[2 * q]     = ffma2(ipA, wv.x, accA[2 * q]);
                        accA[2 * q + 1] = ffma2(ipA, wv.y, accA[2 * q + 1]);
                        accB[2 * q]     = ffma2(ipB, wv.x, accB[2 * q]);
                        accB[2 * q + 1] = ffma2(ipB, wv.y, accB[2 * q + 1]);
                    }
                }
            }
        }
    }

    // write out both pixels
    #pragma unroll
    for (int pix = 0; pix < 2; ++pix) {
        const u64* acc = pix ? accB : accA;
        const int p = (y0 + ty + pix * 4) * HW + x;
        if (g <= 1) {
            __nv_bfloat16* dst = (g == 0 ? g_Qs : g_Ks) + (size_t)(b * NPIX + p) * 64;
            #pragma unroll
            for (int u = 0; u < 16; ++u) {
                float2 v = funpack2(acc[u]);
                __nv_bfloat162 hh = __floats2bfloat162_rn(v.x, v.y);
                __nv_bfloat162 ll = __floats2bfloat162_rn(
                    v.x - __bfloat162float(hh.x), v.y - __bfloat162float(hh.y));
                *reinterpret_cast<__nv_bfloat162*>(dst + 2 * u)      = hh;
                *reinterpret_cast<__nv_bfloat162*>(dst + 32 + 2 * u) = ll;
            }
        } else {
            __half* dst = g_V + (size_t)(b * NPIX + p) * 64 + (g - 2) * 32;
            #pragma unroll
            for (int u = 0; u < 16; ++u) {
                float2 v = funpack2(acc[u]);
                *reinterpret_cast<__half2*>(dst + 2 * u) = __floats2half2_rn(v.x, v.y);
            }
        }
    }
}

// ---------------------------------------------------------------------------
// Tensor-core flash attention (unchanged from R14 / R11).
// ---------------------------------------------------------------------------
#define ATTN_SMEM (5 * 9216)

__global__ __launch_bounds__(128)
void attn_kernel(const float* __restrict__ A1C, float* __restrict__ out) {
    extern __shared__ __align__(16) char sm[];
    char* Qs  = sm;
    char* Kb0 = sm + 9216;
    char* Vb0 = sm + 27648;
    float* Of = reinterpret_cast<float*>(sm + 9216);

    const int rb   = blockIdx.x;
    const int b    = blockIdx.y;
    const int tid  = threadIdx.x;
    const int lane = tid & 31;
    const int w    = tid >> 5;
    const int q0   = rb * 64;
    const char* gQ = (const char*)(g_Qs + (size_t)(b * NPIX + q0) * 64);
    const char* gK = (const char*)(g_Ks + (size_t)b * NPIX * 64);
    const char* gV = (const char*)(g_V  + (size_t)b * NPIX * 64);

    for (int f = tid; f < 512; f += 128) {
        int r = f >> 3, s = (f & 7) * 16;
        cp_async16(Qs  + r * 144 + s, gQ + r * 128 + s);
        cp_async16(Kb0 + r * 144 + s, gK + r * 128 + s);
        cp_async16(Vb0 + r * 144 + s, gV + r * 128 + s);
    }
    CP_COMMIT();
    CP_WAIT0();
    __syncthreads();

    const u32 qrow  = w * 16 + ((lane >> 3) & 1) * 8 + (lane & 7);
    const u32 qcol8 = (lane >> 4) * 8;
    const u32 qbase = (u32)__cvta_generic_to_shared(Qs) + qrow * 144;
    u32 Ah[2][4], Al[2][4];
    ldsm4(Ah[0], qbase + (0  + qcol8) * 2);
    ldsm4(Ah[1], qbase + (16 + qcol8) * 2);
    ldsm4(Al[0], qbase + (32 + qcol8) * 2);
    ldsm4(Al[1], qbase + (48 + qcol8) * 2);

    const u32 koff = (lane & 7) * 144 + (((lane >> 3) & 1) * 8 + (lane >> 4) * 16) * 2;
    const u32 voff = (((lane >> 3) & 1) * 8 + (lane & 7)) * 144 + (lane >> 4) * 16;

    float o[8][4] = {};
    float lsum0 = 0.f, lsum1 = 0.f;
    float m0 = -1e30f, m1 = -1e30f;

    for (int kb = 0; kb < 64; ++kb) {
        const int buf = kb & 1;
        if (kb > 0) {
            CP_WAIT0();
            __syncthreads();
        }
        if (kb < 63) {
            const char* gKn = gK + (size_t)(kb + 1) * 64 * 128;
            const char* gVn = gV + (size_t)(kb + 1) * 64 * 128;
            char* Kn = Kb0 + (buf ^ 1) * 9216;
            char* Vn = Vb0 + (buf ^ 1) * 9216;
            for (int f = tid; f < 512; f += 128) {
                int r = f >> 3, s = (f & 7) * 16;
                cp_async16(Kn + r * 144 + s, gKn + r * 128 + s);
                cp_async16(Vn + r * 144 + s, gVn + r * 128 + s);
            }
        }
        CP_COMMIT();

        const u32 kbase = (u32)__cvta_generic_to_shared(Kb0 + buf * 9216) + koff;
        float c[8][4] = {};
        #pragma unroll
        for (int nt = 0; nt < 8; ++nt) {
            u32 bh[4], bl[4];
            u32 ra = kbase + nt * 8 * 144;
            ldsm4(bh, ra);
            ldsm4(bl, ra + 64);
            mma_bf16(c[nt][0], c[nt][1], c[nt][2], c[nt][3],
                     Ah[0][0], Ah[0][1], Ah[0][2], Ah[0][3], bh[0], bh[1]);
            mma_bf16(c[nt][0], c[nt][1], c[nt][2], c[nt][3],
                     Ah[1][0], Ah[1][1], Ah[1][2], Ah[1][3], bh[2], bh[3]);
            mma_bf16(c[nt][0], c[nt][1], c[nt][2], c[nt][3],
                     Ah[0][0], Ah[0][1], Ah[0][2], Ah[0][3], bl[0], bl[1]);
            mma_bf16(c[nt][0], c[nt][1], c[nt][2], c[nt][3],
                     Ah[1][0], Ah[1][1], Ah[1][2], Ah[1][3], bl[2], bl[3]);
            mma_bf16(c[nt][0], c[nt][1], c[nt][2], c[nt][3],
                     Al[0][0], Al[0][1], Al[0][2], Al[0][3], bh[0], bh[1]);
            mma_bf16(c[nt][0], c[nt][1], c[nt][2], c[nt][3],
                     Al[1][0], Al[1][1], Al[1][2], Al[1][3], bh[2], bh[3]);
        }

        float mx0 = -1e30f, mx1 = -1e30f;
        #pragma unroll
        for (int nt = 0; nt < 8; ++nt) {
            mx0 = fmaxf(mx0, fmaxf(c[nt][0], c[nt][1]));
            mx1 = fmaxf(mx1, fmaxf(c[nt][2], c[nt][3]));
        }
        mx0 = fmaxf(mx0, __shfl_xor_sync(0xffffffffu, mx0, 1));
        mx0 = fmaxf(mx0, __shfl_xor_sync(0xffffffffu, mx0, 2));
        mx1 = fmaxf(mx1, __shfl_xor_sync(0xffffffffu, mx1, 1));
        mx1 = fmaxf(mx1, __shfl_xor_sync(0xffffffffu, mx1, 2));
        float mn0 = fmaxf(m0, mx0), mn1 = fmaxf(m1, mx1);
        if (mn0 > m0 || mn1 > m1) {
            float a0 = ex2f(m0 - mn0), a1 = ex2f(m1 - mn1);
            lsum0 *= a0; lsum1 *= a1;
            #pragma unroll
            for (int ct = 0; ct < 8; ++ct) {
                o[ct][0] *= a0; o[ct][1] *= a0;
                o[ct][2] *= a1; o[ct][3] *= a1;
            }
            m0 = mn0; m1 = mn1;
        }
        u32 Ph[4][4];
        #pragma unroll
        for (int nt = 0; nt < 8; ++nt) {
            float e0 = ex2f(c[nt][0] - m0);
            float e1 = ex2f(c[nt][1] - m0);
            float e2 = ex2f(c[nt][2] - m1);
            float e3 = ex2f(c[nt][3] - m1);
            lsum0 += e0 + e1;
            lsum1 += e2 + e3;
            int kt = nt >> 1, q = (nt & 1) * 2;
            Ph[kt][q]     = h2u(__floats2half2_rn(e0, e1));
            Ph[kt][q + 1] = h2u(__floats2half2_rn(e2, e3));
        }

        const u32 vbase = (u32)__cvta_generic_to_shared(Vb0 + buf * 9216) + voff;
        #pragma unroll
        for (int kt = 0; kt < 4; ++kt) {
            #pragma unroll
            for (int cb = 0; cb < 4; ++cb) {
                u32 vr[4];
                ldsm4t(vr, vbase + kt * 16 * 144 + cb * 32);
                float* oa = o[2 * cb];
                float* ob = o[2 * cb + 1];
                mma_f16(oa[0], oa[1], oa[2], oa[3],
                        Ph[kt][0], Ph[kt][1], Ph[kt][2], Ph[kt][3], vr[0], vr[1]);
                mma_f16(ob[0], ob[1], ob[2], ob[3],
                        Ph[kt][0], Ph[kt][1], Ph[kt][2], Ph[kt][3], vr[2], vr[3]);
            }
        }
    }

    lsum0 += __shfl_xor_sync(0xffffffffu, lsum0, 1);
    lsum0 += __shfl_xor_sync(0xffffffffu, lsum0, 2);
    lsum1 += __shfl_xor_sync(0xffffffffu, lsum1, 1);
    lsum1 += __shfl_xor_sync(0xffffffffu, lsum1, 2);

    __syncthreads();

    {
        float inv0 = 1.f / lsum0, inv1 = 1.f / lsum1;
        int r0 = w * 16 + (lane >> 2);
        int cc = (lane & 3) * 2;
        #pragma unroll
        for (int ct = 0; ct < 8; ++ct) {
            Of[r0 * 65 + ct * 8 + cc]           = o[ct][0] * inv0;
            Of[r0 * 65 + ct * 8 + cc + 1]       = o[ct][1] * inv0;
            Of[(r0 + 8) * 65 + ct * 8 + cc]     = o[ct][2] * inv1;
            Of[(r0 + 8) * 65 + ct * 8 + cc + 1] = o[ct][3] * inv1;
        }
    }
    __syncthreads();

    {
        int ch = tid >> 1, seg = (tid & 1) * 32;
        int gbase = (b * 64 + ch) * NPIX + q0 + seg;
        #pragma unroll
        for (int ww = 0; ww < 32; ww += 4) {
            float4 r = *reinterpret_cast<const float4*>(A1C + gbase + ww);
            float4 oo;
            oo.x = Of[(seg + ww + 0) * 65 + ch] + r.x;
            oo.y = Of[(seg + ww + 1) * 65 + ch] + r.y;
            oo.z = Of[(seg + ww + 2) * 65 + ch] + r.z;
            oo.w = Of[(seg + ww + 3) * 65 + ch] + r.w;
            *reinterpret_cast<float4*>(out + gbase + ww) = oo;
        }
    }
}

// ---------------------------------------------------------------------------
extern "C" void kernel_launch(void* const* d_in, const int* in_sizes, int n_in,
                              void* d_out, int out_size) {
    const float* A1B = (const float*)d_in[0];
    const float* A1C = (const float*)d_in[1];
    const float* w1  = (const float*)d_in[2];
    const float* b1  = (const float*)d_in[3];
    const float* w2  = (const float*)d_in[4];
    const float* b2  = (const float*)d_in[5];
    const float* w3  = (const float*)d_in[6];
    const float* b3  = (const float*)d_in[7];
    float* out = (float*)d_out;

    cudaFuncSetAttribute(conv_kernel, cudaFuncAttributeMaxDynamicSharedMemorySize, CONV_SMEM);
    cudaFuncSetAttribute(attn_kernel, cudaFuncAttributeMaxDynamicSharedMemorySize, ATTN_SMEM);

    pack_kernel<<<288, 256>>>(w1, b1, w2, b2, w3, b3);
    conv_kernel<<<dim3(8, NB, 4), 256, CONV_SMEM>>>(A1B, A1C);
    attn_kernel<<<dim3(NPIX / 64, NB), 128, ATTN_SMEM>>>(A1C, out);
}

// round 17
// speedup vs baseline: 3.4728x; 1.4878x over previous
#include <cuda_runtime.h>
#include <cuda_bf16.h>
#include <cuda_fp16.h>

// ---------------------------------------------------------------------------
// BSAM: tensor-core conv (9-shifted split-bf16 GEMM) + tensor-core attention.
//   Q = conv3x3(A1_B, w1*log2e, b1*log2e) -> g_Qs [b][p][hi32|lo32] bf16
//   K = conv3x3(A1_C, w2,b2)              -> g_Ks [b][p][hi32|lo32] bf16
//   V = conv3x3(A1_C, w3,b3)              -> g_V  [b][p][64] fp16
// R16: conv moved to mma.sync (3-term bf16 split: AhWh+AhWl+AlWh), 128 blocks
//      (2 rows x batch), weights streamed per-tap. Attention unchanged (R11).
// ---------------------------------------------------------------------------

#define NB   4
#define NC   64
#define HW   64
#define NPIX 4096

typedef unsigned long long u64;
typedef unsigned u32;

__device__ __align__(16) __nv_bfloat16 g_Qs[NB * NPIX * 64];
__device__ __align__(16) __nv_bfloat16 g_Ks[NB * NPIX * 64];
__device__ __align__(16) __half        g_V [NB * NPIX * 64];
__device__ __align__(16) __nv_bfloat16 g_Wh[9 * 128 * 64];  // [tap][co][ci] hi
__device__ __align__(16) __nv_bfloat16 g_Wl[9 * 128 * 64];  // [tap][co][ci] lo
__device__ __align__(16) float g_bias[128];

__device__ __forceinline__ float ex2f(float x) {
    float y; asm("ex2.approx.f32 %0, %1;" : "=f"(y) : "f"(x));
    return y;
}
__device__ __forceinline__ void cp_async16(void* sdst, const void* gsrc) {
    u32 sa = (u32)__cvta_generic_to_shared(sdst);
    asm volatile("cp.async.cg.shared.global [%0], [%1], 16;" :: "r"(sa), "l"(gsrc));
}
#define CP_COMMIT() asm volatile("cp.async.commit_group;")
#define CP_WAIT0()  asm volatile("cp.async.wait_group 0;")
#define CP_WAIT1()  asm volatile("cp.async.wait_group 1;")

__device__ __forceinline__ void mma_bf16(float& c0, float& c1, float& c2, float& c3,
                                         u32 a0, u32 a1, u32 a2, u32 a3,
                                         u32 b0, u32 b1) {
    asm volatile(
        "mma.sync.aligned.m16n8k16.row.col.f32.bf16.bf16.f32 "
        "{%0,%1,%2,%3}, {%4,%5,%6,%7}, {%8,%9}, {%0,%1,%2,%3};"
        : "+f"(c0), "+f"(c1), "+f"(c2), "+f"(c3)
        : "r"(a0), "r"(a1), "r"(a2), "r"(a3), "r"(b0), "r"(b1));
}
__device__ __forceinline__ void mma_f16(float& c0, float& c1, float& c2, float& c3,
                                        u32 a0, u32 a1, u32 a2, u32 a3,
                                        u32 b0, u32 b1) {
    asm volatile(
        "mma.sync.aligned.m16n8k16.row.col.f32.f16.f16.f32 "
        "{%0,%1,%2,%3}, {%4,%5,%6,%7}, {%8,%9}, {%0,%1,%2,%3};"
        : "+f"(c0), "+f"(c1), "+f"(c2), "+f"(c3)
        : "r"(a0), "r"(a1), "r"(a2), "r"(a3), "r"(b0), "r"(b1));
}
__device__ __forceinline__ void ldsm4(u32* r, u32 saddr) {
    asm volatile("ldmatrix.sync.aligned.m8n8.x4.shared.b16 {%0,%1,%2,%3}, [%4];"
        : "=r"(r[0]), "=r"(r[1]), "=r"(r[2]), "=r"(r[3]) : "r"(saddr));
}
__device__ __forceinline__ void ldsm4t(u32* r, u32 saddr) {
    asm volatile("ldmatrix.sync.aligned.m8n8.x4.trans.shared.b16 {%0,%1,%2,%3}, [%4];"
        : "=r"(r[0]), "=r"(r[1]), "=r"(r[2]), "=r"(r[3]) : "r"(saddr));
}
__device__ __forceinline__ u32 h2u(__half2 h) {
    return *reinterpret_cast<u32*>(&h);
}

#define LOG2E 1.4426950408889634f

// ---------------------------------------------------------------------------
// Weight pack -> bf16 hi/lo [tap][co][ci]. co 0..31 w1*log2e | 32..63 w2 | 64..127 w3
// grid 288x256 covers 9*128*64 = 73728 exactly.
// ---------------------------------------------------------------------------
__global__ void pack_kernel(const float* __restrict__ w1, const float* __restrict__ b1,
                            const float* __restrict__ w2, const float* __restrict__ b2,
                            const float* __restrict__ w3, const float* __restrict__ b3) {
    int idx = blockIdx.x * 256 + threadIdx.x;
    if (idx < 128)
        g_bias[idx] = (idx < 32) ? b1[idx] * LOG2E
                    : (idx < 64) ? b2[idx - 32] : b3[idx - 64];
    if (idx < 9 * 128 * 64) {
        int ci  = idx & 63;
        int co  = (idx >> 6) & 127;
        int tap = idx >> 13;
        float v;
        if (co < 32)       v = w1[(co * 64 + ci) * 9 + tap] * LOG2E;
        else if (co < 64)  v = w2[((co - 32) * 64 + ci) * 9 + tap];
        else               v = w3[((co - 64) * 64 + ci) * 9 + tap];
        __nv_bfloat16 h = __float2bfloat16(v);
        g_Wh[idx] = h;
        g_Wl[idx] = __float2bfloat16(v - __bfloat162float(h));
    }
}

// ---------------------------------------------------------------------------
// Conv via tensor cores. Block = (2 output rows, batch); 128 blocks; 256 thr.
// Warp w: 16 pixels (warps 0-3 -> row y0 x=16w.., warps 4-7 -> row y0+1) x 128 co.
// SMEM (bytes):
//   sABh@0 sABl@38016 sACh@76032 sACl@114048  : [4r*66xx rows][72 bf16 pitch]
//   sW@152064 : [2 buf][hi 18432 | lo 18432], rows [co][72 bf16]
// 3 split terms per k16: AhWh + AhWl + AlWh (AlWl ~2^-16, dropped).
// ---------------------------------------------------------------------------
#define SAB_H 0
#define SAB_L 38016
#define SAC_H 76032
#define SAC_L 114048
#define SW_OFF 152064
#define CONVM_SMEM (152064 + 2 * 36864)

__device__ __forceinline__ void conv_ldW(char* sm, int buf, int tap, int tid) {
    const char* srcH = (const char*)g_Wh + (size_t)tap * 16384;
    const char* srcL = (const char*)g_Wl + (size_t)tap * 16384;
    char* dst = sm + SW_OFF + buf * 36864;
    #pragma unroll
    for (int f = tid; f < 1024; f += 256) {
        int co = f >> 3, s = (f & 7) * 16;
        cp_async16(dst + co * 144 + s,         srcH + co * 128 + s);
        cp_async16(dst + 18432 + co * 144 + s, srcL + co * 128 + s);
    }
}

__global__ __launch_bounds__(256)
void conv_kernel(const float* __restrict__ A1B, const float* __restrict__ A1C) {
    extern __shared__ __align__(16) char sm[];
    __nv_bfloat16* sBh = (__nv_bfloat16*)(sm + SAB_H);
    __nv_bfloat16* sBl = (__nv_bfloat16*)(sm + SAB_L);
    __nv_bfloat16* sCh = (__nv_bfloat16*)(sm + SAC_H);
    __nv_bfloat16* sCl = (__nv_bfloat16*)(sm + SAC_L);

    const int y0  = blockIdx.x * 2;
    const int b   = blockIdx.y;
    const int tid = threadIdx.x;
    const int lane = tid & 31;
    const int w    = tid >> 5;

    // weights: prefetch taps 0 and 1
    conv_ldW(sm, 0, 0, tid);
    CP_COMMIT();
    conv_ldW(sm, 1, 1, tid);
    CP_COMMIT();

    // stage inputs: 4 rows (y0-1..y0+2) x 66 xx x 64 ci, bf16 hi/lo, pixel-major
    for (int idx = tid; idx < 4 * 66 * 64; idx += 256) {
        int r   = idx / 4224;
        int rem = idx % 4224;
        int ci  = rem / 66;
        int xx  = rem % 66;
        int yy  = y0 - 1 + r;
        int xi  = xx - 1;
        float vb = 0.f, vc = 0.f;
        if (yy >= 0 && yy < HW && xi >= 0 && xi < HW) {
            size_t gi = ((size_t)(b * 64 + ci) * HW + yy) * HW + xi;
            vb = __ldg(A1B + gi);
            vc = __ldg(A1C + gi);
        }
        int ro = (r * 66 + xx) * 72 + ci;
        __nv_bfloat16 hb = __float2bfloat16(vb);
        __nv_bfloat16 hc = __float2bfloat16(vc);
        sBh[ro] = hb; sBl[ro] = __float2bfloat16(vb - __bfloat162float(hb));
        sCh[ro] = hc; sCl[ro] = __float2bfloat16(vc - __bfloat162float(hc));
    }

    // fragment geometry (identical pattern to attention QK)
    const int ylocal = w >> 2;              // 0 or 1
    const int x0w    = (w & 3) * 16;
    const int irow   = ((lane >> 3) & 1) * 8 + (lane & 7);   // A tile row 0..15
    const int ciq    = (lane >> 4) * 8;                      // A ci sub-offset
    const u32 smb    = (u32)__cvta_generic_to_shared(sm);
    const u32 koffB  = (lane & 7) * 144 + (((lane >> 3) & 1) * 8 + (lane >> 4) * 16) * 2;

    float c[16][4] = {};

    for (int tap = 0; tap < 9; ++tap) {
        const int buf = tap & 1;
        const int dy = tap / 3, dx = tap % 3;
        if (tap < 8) CP_WAIT1(); else CP_WAIT0();
        __syncthreads();                      // sW[buf] visible (+ staging on tap 0)

        // A row index in sA: ((ylocal+dy)*66 + x + dx)
        const u32 arow = (u32)(((ylocal + dy) * 66 + x0w + irow + dx) * 72 + ciq) * 2;
        const u32 bbase = smb + SW_OFF + buf * 36864;

        u32 aH[4][4], aL[4][4];

        // ---- group Q (nt 0..3): input B ------------------------------------
        #pragma unroll
        for (int kc = 0; kc < 4; ++kc) {
            ldsm4(aH[kc], smb + SAB_H + arow + kc * 32);
            ldsm4(aL[kc], smb + SAB_L + arow + kc * 32);
        }
        #pragma unroll
        for (int nt = 0; nt < 4; ++nt) {
            u32 ra = bbase + nt * 8 * 144 + koffB;
            u32 bhA[4], bhB[4], blA[4], blB[4];
            ldsm4(bhA, ra);
            ldsm4(bhB, ra + 64);
            ldsm4(blA, ra + 18432);
            ldsm4(blB, ra + 18432 + 64);
            const u32* bsel[4][2] = {{&bhA[0], &blA[0]}, {&bhA[2], &blA[2]},
                                     {&bhB[0], &blB[0]}, {&bhB[2], &blB[2]}};
            #pragma unroll
            for (int kc = 0; kc < 4; ++kc) {
                const u32* bh = bsel[kc][0];
                const u32* bl = bsel[kc][1];
                mma_bf16(c[nt][0], c[nt][1], c[nt][2], c[nt][3],
                         aH[kc][0], aH[kc][1], aH[kc][2], aH[kc][3], bh[0], bh[1]);
                mma_bf16(c[nt][0], c[nt][1], c[nt][2], c[nt][3],
                         aH[kc][0], aH[kc][1], aH[kc][2], aH[kc][3], bl[0], bl[1]);
                mma_bf16(c[nt][0], c[nt][1], c[nt][2], c[nt][3],
                         aL[kc][0], aL[kc][1], aL[kc][2], aL[kc][3], bh[0], bh[1]);
            }
        }

        // ---- group K/V (nt 4..15): input C ---------------------------------
        #pragma unroll
        for (int kc = 0; kc < 4; ++kc) {
            ldsm4(aH[kc], smb + SAC_H + arow + kc * 32);
            ldsm4(aL[kc], smb + SAC_L + arow + kc * 32);
        }
        #pragma unroll
        for (int nt = 4; nt < 16; ++nt) {
            u32 ra = bbase + nt * 8 * 144 + koffB;
            u32 bhA[4], bhB[4], blA[4], blB[4];
            ldsm4(bhA, ra);
            ldsm4(bhB, ra + 64);
            ldsm4(blA, ra + 18432);
            ldsm4(blB, ra + 18432 + 64);
            const u32* bsel[4][2] = {{&bhA[0], &blA[0]}, {&bhA[2], &blA[2]},
                                     {&bhB[0], &blB[0]}, {&bhB[2], &blB[2]}};
            #pragma unroll
            for (int kc = 0; kc < 4; ++kc) {
                const u32* bh = bsel[kc][0];
                const u32* bl = bsel[kc][1];
                mma_bf16(c[nt][0], c[nt][1], c[nt][2], c[nt][3],
                         aH[kc][0], aH[kc][1], aH[kc][2], aH[kc][3], bh[0], bh[1]);
                mma_bf16(c[nt][0], c[nt][1], c[nt][2], c[nt][3],
                         aH[kc][0], aH[kc][1], aH[kc][2], aH[kc][3], bl[0], bl[1]);
                mma_bf16(c[nt][0], c[nt][1], c[nt][2], c[nt][3],
                         aL[kc][0], aL[kc][1], aL[kc][2], aL[kc][3], bh[0], bh[1]);
            }
        }

        __syncthreads();                      // all reads of sW[buf] done
        if (tap < 7) {
            conv_ldW(sm, buf, tap + 2, tid);
            CP_COMMIT();
        }
    }

    // ---- epilogue: bias + split/convert + store -----------------------------
    {
        const int r0 = lane >> 2;
        const int cc = (lane & 3) * 2;
        const int yglob = y0 + ylocal;
        const size_t Pbase = (size_t)b * NPIX + yglob * 64;
        #pragma unroll
        for (int nt = 0; nt < 16; ++nt) {
            const int co = nt * 8 + cc;
            const float b0 = g_bias[co], b1 = g_bias[co + 1];
            #pragma unroll
            for (int half = 0; half < 2; ++half) {
                const int px = x0w + r0 + half * 8;
                const size_t P = Pbase + px;
                float v0 = c[nt][2 * half]     + b0;
                float v1 = c[nt][2 * half + 1] + b1;
                if (co < 64) {
                    __nv_bfloat16* dst = (co < 32 ? g_Qs : g_Ks) + P * 64 + (co & 31);
                    __nv_bfloat162 hh = __floats2bfloat162_rn(v0, v1);
                    __nv_bfloat162 ll = __floats2bfloat162_rn(
                        v0 - __bfloat162float(hh.x), v1 - __bfloat162float(hh.y));
                    *reinterpret_cast<__nv_bfloat162*>(dst)      = hh;
                    *reinterpret_cast<__nv_bfloat162*>(dst + 32) = ll;
                } else {
                    __half* dst = g_V + P * 64 + (co - 64);
                    *reinterpret_cast<__half2*>(dst) = __floats2half2_rn(v0, v1);
                }
            }
        }
    }
}

// ---------------------------------------------------------------------------
// Tensor-core flash attention (unchanged from R15 / R11).
// ---------------------------------------------------------------------------
#define ATTN_SMEM (5 * 9216)

__global__ __launch_bounds__(128)
void attn_kernel(const float* __restrict__ A1C, float* __restrict__ out) {
    extern __shared__ __align__(16) char sma[];
    char* Qs  = sma;
    char* Kb0 = sma + 9216;
    char* Vb0 = sma + 27648;
    float* Of = reinterpret_cast<float*>(sma + 9216);

    const int rb   = blockIdx.x;
    const int b    = blockIdx.y;
    const int tid  = threadIdx.x;
    const int lane = tid & 31;
    const int w    = tid >> 5;
    const int q0   = rb * 64;
    const char* gQ = (const char*)(g_Qs + (size_t)(b * NPIX + q0) * 64);
    const char* gK = (const char*)(g_Ks + (size_t)b * NPIX * 64);
    const char* gV = (const char*)(g_V  + (size_t)b * NPIX * 64);

    for (int f = tid; f < 512; f += 128) {
        int r = f >> 3, s = (f & 7) * 16;
        cp_async16(Qs  + r * 144 + s, gQ + r * 128 + s);
        cp_async16(Kb0 + r * 144 + s, gK + r * 128 + s);
        cp_async16(Vb0 + r * 144 + s, gV + r * 128 + s);
    }
    CP_COMMIT();
    CP_WAIT0();
    __syncthreads();

    const u32 qrow  = w * 16 + ((lane >> 3) & 1) * 8 + (lane & 7);
    const u32 qcol8 = (lane >> 4) * 8;
    const u32 qbase = (u32)__cvta_generic_to_shared(Qs) + qrow * 144;
    u32 Ah[2][4], Al[2][4];
    ldsm4(Ah[0], qbase + (0  + qcol8) * 2);
    ldsm4(Ah[1], qbase + (16 + qcol8) * 2);
    ldsm4(Al[0], qbase + (32 + qcol8) * 2);
    ldsm4(Al[1], qbase + (48 + qcol8) * 2);

    const u32 koff = (lane & 7) * 144 + (((lane >> 3) & 1) * 8 + (lane >> 4) * 16) * 2;
    const u32 voff = (((lane >> 3) & 1) * 8 + (lane & 7)) * 144 + (lane >> 4) * 16;

    float o[8][4] = {};
    float lsum0 = 0.f, lsum1 = 0.f;
    float m0 = -1e30f, m1 = -1e30f;

    for (int kb = 0; kb < 64; ++kb) {
        const int buf = kb & 1;
        if (kb > 0) {
            CP_WAIT0();
            __syncthreads();
        }
        if (kb < 63) {
            const char* gKn = gK + (size_t)(kb + 1) * 64 * 128;
            const char* gVn = gV + (size_t)(kb + 1) * 64 * 128;
            char* Kn = Kb0 + (buf ^ 1) * 9216;
            char* Vn = Vb0 + (buf ^ 1) * 9216;
            for (int f = tid; f < 512; f += 128) {
                int r = f >> 3, s = (f & 7) * 16;
                cp_async16(Kn + r * 144 + s, gKn + r * 128 + s);
                cp_async16(Vn + r * 144 + s, gVn + r * 128 + s);
            }
        }
        CP_COMMIT();

        const u32 kbase = (u32)__cvta_generic_to_shared(Kb0 + buf * 9216) + koff;
        float c[8][4] = {};
        #pragma unroll
        for (int nt = 0; nt < 8; ++nt) {
            u32 bh[4], bl[4];
            u32 ra = kbase + nt * 8 * 144;
            ldsm4(bh, ra);
            ldsm4(bl, ra + 64);
            mma_bf16(c[nt][0], c[nt][1], c[nt][2], c[nt][3],
                     Ah[0][0], Ah[0][1], Ah[0][2], Ah[0][3], bh[0], bh[1]);
            mma_bf16(c[nt][0], c[nt][1], c[nt][2], c[nt][3],
                     Ah[1][0], Ah[1][1], Ah[1][2], Ah[1][3], bh[2], bh[3]);
            mma_bf16(c[nt][0], c[nt][1], c[nt][2], c[nt][3],
                     Ah[0][0], Ah[0][1], Ah[0][2], Ah[0][3], bl[0], bl[1]);
            mma_bf16(c[nt][0], c[nt][1], c[nt][2], c[nt][3],
                     Ah[1][0], Ah[1][1], Ah[1][2], Ah[1][3], bl[2], bl[3]);
            mma_bf16(c[nt][0], c[nt][1], c[nt][2], c[nt][3],
                     Al[0][0], Al[0][1], Al[0][2], Al[0][3], bh[0], bh[1]);
            mma_bf16(c[nt][0], c[nt][1], c[nt][2], c[nt][3],
                     Al[1][0], Al[1][1], Al[1][2], Al[1][3], bh[2], bh[3]);
        }

        float mx0 = -1e30f, mx1 = -1e30f;
        #pragma unroll
        for (int nt = 0; nt < 8; ++nt) {
            mx0 = fmaxf(mx0, fmaxf(c[nt][0], c[nt][1]));
            mx1 = fmaxf(mx1, fmaxf(c[nt][2], c[nt][3]));
        }
        mx0 = fmaxf(mx0, __shfl_xor_sync(0xffffffffu, mx0, 1));
        mx0 = fmaxf(mx0, __shfl_xor_sync(0xffffffffu, mx0, 2));
        mx1 = fmaxf(mx1, __shfl_xor_sync(0xffffffffu, mx1, 1));
        mx1 = fmaxf(mx1, __shfl_xor_sync(0xffffffffu, mx1, 2));
        float mn0 = fmaxf(m0, mx0), mn1 = fmaxf(m1, mx1);
        if (mn0 > m0 || mn1 > m1) {
            float a0 = ex2f(m0 - mn0), a1 = ex2f(m1 - mn1);
            lsum0 *= a0; lsum1 *= a1;
            #pragma unroll
            for (int ct = 0; ct < 8; ++ct) {
                o[ct][0] *= a0; o[ct][1] *= a0;
                o[ct][2] *= a1; o[ct][3] *= a1;
            }
            m0 = mn0; m1 = mn1;
        }
        u32 Ph[4][4];
        #pragma unroll
        for (int nt = 0; nt < 8; ++nt) {
            float e0 = ex2f(c[nt][0] - m0);
            float e1 = ex2f(c[nt][1] - m0);
            float e2 = ex2f(c[nt][2] - m1);
            float e3 = ex2f(c[nt][3] - m1);
            lsum0 += e0 + e1;
            lsum1 += e2 + e3;
            int kt = nt >> 1, q = (nt & 1) * 2;
            Ph[kt][q]     = h2u(__floats2half2_rn(e0, e1));
            Ph[kt][q + 1] = h2u(__floats2half2_rn(e2, e3));
        }

        const u32 vbase = (u32)__cvta_generic_to_shared(Vb0 + buf * 9216) + voff;
        #pragma unroll
        for (int kt = 0; kt < 4; ++kt) {
            #pragma unroll
            for (int cb = 0; cb < 4; ++cb) {
                u32 vr[4];
                ldsm4t(vr, vbase + kt * 16 * 144 + cb * 32);
                float* oa = o[2 * cb];
                float* ob = o[2 * cb + 1];
                mma_f16(oa[0], oa[1], oa[2], oa[3],
                        Ph[kt][0], Ph[kt][1], Ph[kt][2], Ph[kt][3], vr[0], vr[1]);
                mma_f16(ob[0], ob[1], ob[2], ob[3],
                        Ph[kt][0], Ph[kt][1], Ph[kt][2], Ph[kt][3], vr[2], vr[3]);
            }
        }
    }

    lsum0 += __shfl_xor_sync(0xffffffffu, lsum0, 1);
    lsum0 += __shfl_xor_sync(0xffffffffu, lsum0, 2);
    lsum1 += __shfl_xor_sync(0xffffffffu, lsum1, 1);
    lsum1 += __shfl_xor_sync(0xffffffffu, lsum1, 2);

    __syncthreads();

    {
        float inv0 = 1.f / lsum0, inv1 = 1.f / lsum1;
        int r0 = w * 16 + (lane >> 2);
        int cc = (lane & 3) * 2;
        #pragma unroll
        for (int ct = 0; ct < 8; ++ct) {
            Of[r0 * 65 + ct * 8 + cc]           = o[ct][0] * inv0;
            Of[r0 * 65 + ct * 8 + cc + 1]       = o[ct][1] * inv0;
            Of[(r0 + 8) * 65 + ct * 8 + cc]     = o[ct][2] * inv1;
            Of[(r0 + 8) * 65 + ct * 8 + cc + 1] = o[ct][3] * inv1;
        }
    }
    __syncthreads();

    {
        int ch = tid >> 1, seg = (tid & 1) * 32;
        int gbase = (b * 64 + ch) * NPIX + q0 + seg;
        #pragma unroll
        for (int ww = 0; ww < 32; ww += 4) {
            float4 r = *reinterpret_cast<const float4*>(A1C + gbase + ww);
            float4 oo;
            oo.x = Of[(seg + ww + 0) * 65 + ch] + r.x;
            oo.y = Of[(seg + ww + 1) * 65 + ch] + r.y;
            oo.z = Of[(seg + ww + 2) * 65 + ch] + r.z;
            oo.w = Of[(seg + ww + 3) * 65 + ch] + r.w;
            *reinterpret_cast<float4*>(out + gbase + ww) = oo;
        }
    }
}

// ---------------------------------------------------------------------------
extern "C" void kernel_launch(void* const* d_in, const int* in_sizes, int n_in,
                              void* d_out, int out_size) {
    const float* A1B = (const float*)d_in[0];
    const float* A1C = (const float*)d_in[1];
    const float* w1  = (const float*)d_in[2];
    const float* b1  = (const float*)d_in[3];
    const float* w2  = (const float*)d_in[4];
    const float* b2  = (const float*)d_in[5];
    const float* w3  = (const float*)d_in[6];
    const float* b3  = (const float*)d_in[7];
    float* out = (float*)d_out;

    cudaFuncSetAttribute(conv_kernel, cudaFuncAttributeMaxDynamicSharedMemorySize, CONVM_SMEM);
    cudaFuncSetAttribute(attn_kernel, cudaFuncAttributeMaxDynamicSharedMemorySize, ATTN_SMEM);

    pack_kernel<<<288, 256>>>(w1, b1, w2, b2, w3, b3);
    conv_kernel<<<dim3(32, NB), 256, CONVM_SMEM>>>(A1B, A1C);
    attn_kernel<<<dim3(NPIX / 64, NB), 128, ATTN_SMEM>>>(A1C, out);
}